// round 12
// baseline (speedup 1.0000x reference)
#include <cuda_runtime.h>
#include <cuda_bf16.h>
#include <cstdint>

// Problem constants
#define BB 2
#define SS 2048
#define DD 1024
#define HH 16
#define HD 64
#define N3 3072
#define MROWS 4096

// d_out layout
#define A_SZ   ((long long)BB * SS * DD)
#define P_HALF ((long long)BB * HH * SS * HD)
#define P_OFF  (A_SZ)
#define ATTN_OFF (A_SZ + 2 * P_HALF)

// Scratch (device globals)
__device__ __nv_bfloat16 g_xhi[MROWS * DD], g_xlo[MROWS * DD];
__device__ __nv_bfloat16 g_wahi[N3 * DD],  g_walo[N3 * DD];    // w_attn^T [3072,1024]
__device__ __nv_bfloat16 g_wphi[DD * DD],  g_wplo[DD * DD];    // w_proj^T [1024,1024]
__device__ __nv_bfloat16 g_ahhi[MROWS * DD], g_ahlo[MROWS * DD];
#define QKV_N (BB * HH * SS * HD)
__device__ __nv_bfloat16 g_qh[QKV_N], g_ql[QKV_N];
__device__ __nv_bfloat16 g_kh[QKV_N], g_kl[QKV_N];
__device__ __nv_bfloat16 g_vh[QKV_N], g_vl[QKV_N];

// ====================== base-PTX helpers ====================================
__device__ __forceinline__ uint32_t smem_u32(const void* p) {
    uint32_t a;
    asm("{ .reg .u64 t; cvta.to.shared.u64 t, %1; cvt.u32.u64 %0, t; }"
        : "=r"(a) : "l"(p));
    return a;
}
__device__ __forceinline__ void cpa16(uint32_t s, const void* g) {
    asm volatile("cp.async.cg.shared.global [%0], [%1], 16;" :: "r"(s), "l"(g));
}
#define CP_COMMIT() asm volatile("cp.async.commit_group;" ::: "memory")
#define CP_WAIT(n)  asm volatile("cp.async.wait_group %0;" :: "n"(n) : "memory")

__device__ __forceinline__ void ldsm4(uint32_t* r, uint32_t a) {
    asm volatile("ldmatrix.sync.aligned.m8n8.x4.shared.b16 {%0,%1,%2,%3}, [%4];"
                 : "=r"(r[0]), "=r"(r[1]), "=r"(r[2]), "=r"(r[3]) : "r"(a));
}
__device__ __forceinline__ void ldsm2(uint32_t* r, uint32_t a) {
    asm volatile("ldmatrix.sync.aligned.m8n8.x2.shared.b16 {%0,%1}, [%2];"
                 : "=r"(r[0]), "=r"(r[1]) : "r"(a));
}
__device__ __forceinline__ void ldsm2t(uint32_t* r, uint32_t a) {
    asm volatile("ldmatrix.sync.aligned.m8n8.x2.trans.shared.b16 {%0,%1}, [%2];"
                 : "=r"(r[0]), "=r"(r[1]) : "r"(a));
}
__device__ __forceinline__ void mma_bf16(float* d, const uint32_t* a, const uint32_t* b) {
    asm volatile("mma.sync.aligned.m16n8k16.row.col.f32.bf16.bf16.f32 "
                 "{%0,%1,%2,%3}, {%4,%5,%6,%7}, {%8,%9}, {%0,%1,%2,%3};"
                 : "+f"(d[0]), "+f"(d[1]), "+f"(d[2]), "+f"(d[3])
                 : "r"(a[0]), "r"(a[1]), "r"(a[2]), "r"(a[3]), "r"(b[0]), "r"(b[1]));
}
__device__ __forceinline__ void sp(float x, uint16_t& h, uint16_t& l) {
    __nv_bfloat16 bh = __float2bfloat16_rn(x);
    h = __bfloat16_as_ushort(bh);
    l = __bfloat16_as_ushort(__float2bfloat16_rn(x - __bfloat162float(bh)));
}
__device__ __forceinline__ uint32_t pk(uint16_t a, uint16_t b) {
    return (uint32_t)a | ((uint32_t)b << 16);
}

// ====================== bf16 split kernels ==================================
__global__ __launch_bounds__(256) void split_plain(const float* __restrict__ in,
                                                   __nv_bfloat16* __restrict__ hi,
                                                   __nv_bfloat16* __restrict__ lo, int n4) {
    int i = blockIdx.x * 256 + threadIdx.x;
    if (i >= n4) return;
    float4 v = ((const float4*)in)[i];
    uint16_t h0, h1, h2, h3, l0, l1, l2, l3;
    sp(v.x, h0, l0); sp(v.y, h1, l1); sp(v.z, h2, l2); sp(v.w, h3, l3);
    ((uint2*)hi)[i] = make_uint2(pk(h0, h1), pk(h2, h3));
    ((uint2*)lo)[i] = make_uint2(pk(l0, l1), pk(l2, l3));
}

__global__ __launch_bounds__(256) void split_T(const float* __restrict__ in,
                                               __nv_bfloat16* __restrict__ hi,
                                               __nv_bfloat16* __restrict__ lo, int N) {
    __shared__ float t[32][33];
    int nb = blockIdx.x * 32, kb = blockIdx.y * 32;
#pragma unroll
    for (int r = 0; r < 4; r++)
        t[threadIdx.y + r * 8][threadIdx.x] =
            in[(long long)(kb + threadIdx.y + r * 8) * N + nb + threadIdx.x];
    __syncthreads();
#pragma unroll
    for (int r = 0; r < 4; r++) {
        int n = nb + threadIdx.y + r * 8;
        float v = t[threadIdx.x][threadIdx.y + r * 8];
        uint16_t h, l;
        sp(v, h, l);
        long long o = (long long)n * 1024 + kb + threadIdx.x;
        hi[o] = __ushort_as_bfloat16(h);
        lo[o] = __ushort_as_bfloat16(l);
    }
}

// ====================== pipelined mma.sync GEMM (bf16x3) ====================
#define GPB 80
#define GT_TILEB (128 * GPB)           // 10240
#define GT_STAGEB (4 * GT_TILEB)       // 40960
#define GEMM_SMEM (2 * GT_STAGEB)      // 81920

template <int MODE>
__global__ __launch_bounds__(256, 2) void gemm_mma(
    const __nv_bfloat16* __restrict__ Ahi, const __nv_bfloat16* __restrict__ Alo,
    const __nv_bfloat16* __restrict__ Bhi, const __nv_bfloat16* __restrict__ Blo,
    const float* __restrict__ bias, float* __restrict__ out) {
    extern __shared__ char smm[];
    const uint32_t sb = smem_u32(smm);
    const int tid = threadIdx.x;
    const int lane = tid & 31, warp = tid >> 5;
    const int wm = warp >> 1, wn = warp & 1;
    const int qr = lane >> 2, qc2 = (lane & 3) * 2;
    const int nbase = blockIdx.x * 128, rbase = blockIdx.y * 128;

    float o[2][8][4];
#pragma unroll
    for (int a = 0; a < 2; a++)
#pragma unroll
        for (int b = 0; b < 8; b++)
#pragma unroll
            for (int c = 0; c < 4; c++) o[a][b][c] = 0.f;

    const char* srcs[4] = {
        (const char*)(Ahi + (long long)rbase * 1024),
        (const char*)(Alo + (long long)rbase * 1024),
        (const char*)(Bhi + (long long)nbase * 1024),
        (const char*)(Blo + (long long)nbase * 1024)};

    // prologue: load stage 0
#pragma unroll
    for (int i = 0; i < 8; i++) {
        int idx = tid + i * 256;
        int t = idx >> 9, q = idx & 511, r = q >> 2, c = q & 3;
        cpa16(sb + t * GT_TILEB + r * GPB + c * 16,
              srcs[t] + (long long)r * 2048 + c * 16);
    }
    CP_COMMIT();

    for (int ks = 0; ks < 32; ks++) {
        if (ks + 1 < 32) {
            const int kboff = (ks + 1) * 64;
            const uint32_t dstb = sb + ((ks + 1) & 1) * GT_STAGEB;
#pragma unroll
            for (int i = 0; i < 8; i++) {
                int idx = tid + i * 256;
                int t = idx >> 9, q = idx & 511, r = q >> 2, c = q & 3;
                cpa16(dstb + t * GT_TILEB + r * GPB + c * 16,
                      srcs[t] + (long long)r * 2048 + kboff + c * 16);
            }
            CP_COMMIT();
            CP_WAIT(1);
        } else {
            CP_WAIT(0);
        }
        __syncthreads();

        const uint32_t base = sb + (ks & 1) * GT_STAGEB;
#pragma unroll
        for (int j = 0; j < 2; j++) {
            uint32_t ah[2][4], al[2][4];
#pragma unroll
            for (int mt = 0; mt < 2; mt++) {
                uint32_t r = wm * 32 + mt * 16 + (lane & 7) + ((lane >> 3) & 1) * 8;
                uint32_t cb = j * 32 + (lane >> 4) * 16;
                uint32_t off = r * GPB + cb;
                ldsm4(ah[mt], base + off);
                ldsm4(al[mt], base + GT_TILEB + off);
            }
#pragma unroll
            for (int g = 0; g < 2; g++) {
                uint32_t bh[4][2], bl[4][2];
#pragma unroll
                for (int u = 0; u < 4; u++) {
                    int nt = g * 4 + u;
                    uint32_t n = wn * 64 + nt * 8 + (lane & 7);
                    uint32_t cb = j * 32 + ((lane >> 3) & 1) * 16;
                    uint32_t off = n * GPB + cb;
                    ldsm2(bh[u], base + 2 * GT_TILEB + off);
                    ldsm2(bl[u], base + 3 * GT_TILEB + off);
                }
#pragma unroll
                for (int u = 0; u < 4; u++) {
                    mma_bf16(o[0][g * 4 + u], ah[0], bh[u]);
                    mma_bf16(o[1][g * 4 + u], ah[1], bh[u]);
                }
#pragma unroll
                for (int u = 0; u < 4; u++) {
                    mma_bf16(o[0][g * 4 + u], ah[0], bl[u]);
                    mma_bf16(o[1][g * 4 + u], ah[1], bl[u]);
                }
#pragma unroll
                for (int u = 0; u < 4; u++) {
                    mma_bf16(o[0][g * 4 + u], al[0], bh[u]);
                    mma_bf16(o[1][g * 4 + u], al[1], bh[u]);
                }
            }
        }
        __syncthreads();
    }

    // epilogue
#pragma unroll
    for (int nt = 0; nt < 8; nt++) {
        const int cg = nbase + wn * 64 + nt * 8 + qc2;
        const float b0 = bias[cg], b1 = bias[cg + 1];
#pragma unroll
        for (int mt = 0; mt < 2; mt++) {
            int r0 = rbase + wm * 32 + mt * 16 + qr;
            int r1 = r0 + 8;
            float2 v0 = make_float2(o[mt][nt][0] + b0, o[mt][nt][1] + b1);
            float2 v1 = make_float2(o[mt][nt][2] + b0, o[mt][nt][3] + b1);
            if (MODE == 0) {
                int which = cg >> 10, d0 = cg & 1023;
                int hh = d0 >> 6, e0 = d0 & 63;
                int b_0 = r0 >> 11, s_0 = r0 & 2047;
                int b_1 = r1 >> 11, s_1 = r1 & 2047;
                long long i0 = (((long long)(b_0 * HH + hh)) * SS + s_0) * HD + e0;
                long long i1 = (((long long)(b_1 * HH + hh)) * SS + s_1) * HD + e0;
                uint16_t h0, h1, h2, h3, l0, l1, l2, l3;
                sp(v0.x, h0, l0); sp(v0.y, h1, l1);
                sp(v1.x, h2, l2); sp(v1.y, h3, l3);
                if (which == 0) {
                    *(uint32_t*)&g_qh[i0] = pk(h0, h1); *(uint32_t*)&g_ql[i0] = pk(l0, l1);
                    *(uint32_t*)&g_qh[i1] = pk(h2, h3); *(uint32_t*)&g_ql[i1] = pk(l2, l3);
                } else if (which == 1) {
                    *(float2*)&out[P_OFF + i0] = v0;
                    *(float2*)&out[P_OFF + i1] = v1;
                    *(uint32_t*)&g_kh[i0] = pk(h0, h1); *(uint32_t*)&g_kl[i0] = pk(l0, l1);
                    *(uint32_t*)&g_kh[i1] = pk(h2, h3); *(uint32_t*)&g_kl[i1] = pk(l2, l3);
                } else {
                    *(float2*)&out[P_OFF + P_HALF + i0] = v0;
                    *(float2*)&out[P_OFF + P_HALF + i1] = v1;
                    *(uint32_t*)&g_vh[i0] = pk(h0, h1); *(uint32_t*)&g_vl[i0] = pk(l0, l1);
                    *(uint32_t*)&g_vh[i1] = pk(h2, h3); *(uint32_t*)&g_vl[i1] = pk(l2, l3);
                }
            } else {
                *(float2*)&out[(long long)r0 * DD + cg] = v0;
                *(float2*)&out[(long long)r1 * DD + cg] = v1;
            }
        }
    }
}

// ====================== attention (single pass + fused rescale) =============
#define APB 144
#define QT_B (128 * APB)
#define KT_B (64 * APB)
#define KSTAGE (4 * KT_B)
#define KBASE (2 * QT_B)
#define ATTN_SMEM (2 * QT_B + 2 * KSTAGE)   // 110592 -> 2 CTAs/SM

__global__ __launch_bounds__(256, 2) void attn_mma(float* __restrict__ out) {
    extern __shared__ char smm[];
    const uint32_t sb = smem_u32(smm);
    const int tid = threadIdx.x;
    const int lane = tid & 31, wm = tid >> 5;
    const int qr = lane >> 2, qc2 = (lane & 3) * 2;
    const int qt = (gridDim.x - 1) - blockIdx.x;
    const int h = blockIdx.y, b = blockIdx.z;
    const int qbase = qt * 128;
    const int bh_ = b * HH + h;
    const long long hoff = (long long)bh_ * SS * HD;
    const char* qhg = (const char*)(g_qh + hoff + (long long)qbase * HD);
    const char* qlg = (const char*)(g_ql + hoff + (long long)qbase * HD);
    const char* khg = (const char*)(g_kh + hoff);
    const char* klg = (const char*)(g_kl + hoff);
    const char* vhg = (const char*)(g_vh + hoff);
    const char* vlg = (const char*)(g_vl + hoff);
    float* attn_out = out + ATTN_OFF + (long long)bh_ * SS * SS;
    const int nkt = 2 * qt + 2;

    // load Q hi/lo
#pragma unroll
    for (int i = 0; i < 4; i++) {
        int idx = tid + i * 256;
        int r = idx >> 3, c = idx & 7;
        cpa16(sb + r * APB + c * 16, qhg + idx * 16);
        cpa16(sb + QT_B + r * APB + c * 16, qlg + idx * 16);
    }
    CP_COMMIT();

    // K+V tile 0 into stage 0
#pragma unroll
    for (int i = 0; i < 2; i++) {
        int idx = tid + i * 256;
        int r = idx >> 3, c = idx & 7;
        uint32_t db = sb + KBASE;
        cpa16(db + r * APB + c * 16, khg + idx * 16);
        cpa16(db + KT_B + r * APB + c * 16, klg + idx * 16);
        cpa16(db + 2 * KT_B + r * APB + c * 16, vhg + idx * 16);
        cpa16(db + 3 * KT_B + r * APB + c * 16, vlg + idx * 16);
    }
    CP_COMMIT();
    CP_WAIT(1);
    __syncthreads();

    uint32_t qh[4][4], ql[4][4];
#pragma unroll
    for (int j = 0; j < 4; j++) {
        uint32_t r = wm * 16 + (lane & 7) + ((lane >> 3) & 1) * 8;
        uint32_t c = j * 16 + (lane >> 4) * 8;
        uint32_t off = r * APB + c * 2;
        ldsm4(qh[j], sb + off);
        ldsm4(ql[j], sb + QT_B + off);
    }

    const int r0g = qbase + wm * 16 + qr;
    const int r1g = r0g + 8;

    float rs0 = 0.f, rs1 = 0.f;
    float o[8][4];
#pragma unroll
    for (int a = 0; a < 8; a++)
#pragma unroll
        for (int c = 0; c < 4; c++) o[a][c] = 0.f;

    for (int kt = 0; kt < nkt; kt++) {
        if (kt + 1 < nkt) {
            const uint32_t db = sb + KBASE + ((kt + 1) & 1) * KSTAGE;
            const long long go = (long long)(kt + 1) * 8192;
#pragma unroll
            for (int i = 0; i < 2; i++) {
                int idx = tid + i * 256;
                int r = idx >> 3, c = idx & 7;
                cpa16(db + r * APB + c * 16, khg + go + idx * 16);
                cpa16(db + KT_B + r * APB + c * 16, klg + go + idx * 16);
                cpa16(db + 2 * KT_B + r * APB + c * 16, vhg + go + idx * 16);
                cpa16(db + 3 * KT_B + r * APB + c * 16, vlg + go + idx * 16);
            }
            CP_COMMIT();
            CP_WAIT(1);
        } else {
            CP_WAIT(0);
        }
        __syncthreads();

        const uint32_t kb = sb + KBASE + (kt & 1) * KSTAGE;
        // QK^T (bf16 x3)
        float s[8][4];
#pragma unroll
        for (int nt = 0; nt < 8; nt++)
#pragma unroll
            for (int c = 0; c < 4; c++) s[nt][c] = 0.f;
#pragma unroll
        for (int j = 0; j < 4; j++) {
#pragma unroll
            for (int g = 0; g < 2; g++) {
                uint32_t bh2[4][2], bl2[4][2];
#pragma unroll
                for (int u = 0; u < 4; u++) {
                    uint32_t n = (g * 4 + u) * 8 + (lane & 7);
                    uint32_t c = j * 16 + ((lane >> 3) & 1) * 8;
                    uint32_t off = n * APB + c * 2;
                    ldsm2(bh2[u], kb + off);
                    ldsm2(bl2[u], kb + KT_B + off);
                }
#pragma unroll
                for (int u = 0; u < 4; u++) mma_bf16(s[g * 4 + u], qh[j], bh2[u]);
#pragma unroll
                for (int u = 0; u < 4; u++) mma_bf16(s[g * 4 + u], qh[j], bl2[u]);
#pragma unroll
                for (int u = 0; u < 4; u++) mma_bf16(s[g * 4 + u], ql[j], bh2[u]);
            }
        }

        // exp (unnormalized) -> gmem write + rowsum accumulate + S fragments
        uint32_t sah[4][4], sal[4][4];
#pragma unroll
        for (int nt = 0; nt < 8; nt++) {
            const int cg = kt * 64 + nt * 8 + qc2;
            float e0 = (cg > r0g)     ? 0.f : __expf(s[nt][0] * 0.125f);
            float e1 = (cg + 1 > r0g) ? 0.f : __expf(s[nt][1] * 0.125f);
            float e2 = (cg > r1g)     ? 0.f : __expf(s[nt][2] * 0.125f);
            float e3 = (cg + 1 > r1g) ? 0.f : __expf(s[nt][3] * 0.125f);
            rs0 += e0 + e1;
            rs1 += e2 + e3;
            *(float2*)&attn_out[(long long)r0g * SS + cg] = make_float2(e0, e1);
            *(float2*)&attn_out[(long long)r1g * SS + cg] = make_float2(e2, e3);
            uint16_t h0, h1, h2, h3, l0, l1, l2, l3;
            sp(e0, h0, l0); sp(e1, h1, l1); sp(e2, h2, l2); sp(e3, h3, l3);
            const int j = nt >> 1, half = (nt & 1) * 2;
            sah[j][half] = pk(h0, h1); sah[j][half + 1] = pk(h2, h3);
            sal[j][half] = pk(l0, l1); sal[j][half + 1] = pk(l2, l3);
        }
        // A@V (unnormalized, bf16 x3)
#pragma unroll
        for (int j = 0; j < 4; j++) {
#pragma unroll
            for (int g = 0; g < 2; g++) {
                uint32_t vh2[4][2], vl2[4][2];
#pragma unroll
                for (int u = 0; u < 4; u++) {
                    uint32_t key = j * 16 + ((lane >> 3) & 1) * 8 + (lane & 7);
                    uint32_t off = key * APB + (g * 4 + u) * 16;
                    ldsm2t(vh2[u], kb + 2 * KT_B + off);
                    ldsm2t(vl2[u], kb + 3 * KT_B + off);
                }
#pragma unroll
                for (int u = 0; u < 4; u++) mma_bf16(o[g * 4 + u], sah[j], vh2[u]);
#pragma unroll
                for (int u = 0; u < 4; u++) mma_bf16(o[g * 4 + u], sah[j], vl2[u]);
#pragma unroll
                for (int u = 0; u < 4; u++) mma_bf16(o[g * 4 + u], sal[j], vh2[u]);
            }
        }
        __syncthreads();
    }

    // rowsum reduce (within quads; lanes 4q..4q+3 share a row)
    rs0 += __shfl_xor_sync(0xFFFFFFFFu, rs0, 1);
    rs0 += __shfl_xor_sync(0xFFFFFFFFu, rs0, 2);
    rs1 += __shfl_xor_sync(0xFFFFFFFFu, rs1, 1);
    rs1 += __shfl_xor_sync(0xFFFFFFFFu, rs1, 2);
    const float ri0 = 1.0f / rs0;
    const float ri1 = 1.0f / rs1;

    // publish per-row 1/rowsum to smem (reuse K stage area; loop is done)
    float* srinv = (float*)(smm + KBASE);
    if ((lane & 3) == 0) {
        srinv[wm * 16 + qr] = ri0;
        srinv[wm * 16 + qr + 8] = ri1;
    }

    // merged-head output (normalized) as bf16 hi/lo (feeds proj GEMM)
#pragma unroll
    for (int nt2 = 0; nt2 < 8; nt2++) {
        const int col = h * 64 + nt2 * 8 + qc2;
        const long long gr0 = (long long)(b * SS + qbase + wm * 16 + qr);
        uint16_t h0, h1, h2, h3, l0, l1, l2, l3;
        sp(o[nt2][0] * ri0, h0, l0); sp(o[nt2][1] * ri0, h1, l1);
        sp(o[nt2][2] * ri1, h2, l2); sp(o[nt2][3] * ri1, h3, l3);
        *(uint32_t*)&g_ahhi[gr0 * DD + col] = pk(h0, h1);
        *(uint32_t*)&g_ahlo[gr0 * DD + col] = pk(l0, l1);
        *(uint32_t*)&g_ahhi[(gr0 + 8) * DD + col] = pk(h2, h3);
        *(uint32_t*)&g_ahlo[(gr0 + 8) * DD + col] = pk(l2, l3);
    }

    // fused rescale tail: normalize lower-triangle block + zero upper
    __syncthreads();   // srinv visible; all gmem attn writes visible in-block
    const int Lc = nkt * 64;   // (qt+1)*128
    const float4 z = make_float4(0.f, 0.f, 0.f, 0.f);
    for (int i = tid; i < 128 * 512; i += 256) {
        int r = i >> 9;
        int c4 = (i & 511) << 2;
        float4* p = (float4*)&attn_out[(long long)(qbase + r) * SS + c4];
        if (c4 < Lc) {
            float rv = srinv[r];
            float4 v = *p;
            v.x *= rv; v.y *= rv; v.z *= rv; v.w *= rv;
            *p = v;
        } else {
            *p = z;
        }
    }
}

// ====================== launch ==============================================
extern "C" void kernel_launch(void* const* d_in, const int* in_sizes, int n_in,
                              void* d_out, int out_size) {
    const float* x      = (const float*)d_in[0];
    const float* w_attn = (const float*)d_in[1];
    const float* b_attn = (const float*)d_in[2];
    const float* w_proj = (const float*)d_in[3];
    const float* b_proj = (const float*)d_in[4];
    float* out = (float*)d_out;

    __nv_bfloat16 *xhi, *xlo, *wahi, *walo, *wphi, *wplo, *ahhi, *ahlo;
    cudaGetSymbolAddress((void**)&xhi,  g_xhi);
    cudaGetSymbolAddress((void**)&xlo,  g_xlo);
    cudaGetSymbolAddress((void**)&wahi, g_wahi);
    cudaGetSymbolAddress((void**)&walo, g_walo);
    cudaGetSymbolAddress((void**)&wphi, g_wphi);
    cudaGetSymbolAddress((void**)&wplo, g_wplo);
    cudaGetSymbolAddress((void**)&ahhi, g_ahhi);
    cudaGetSymbolAddress((void**)&ahlo, g_ahlo);

    cudaFuncSetAttribute(gemm_mma<0>, cudaFuncAttributeMaxDynamicSharedMemorySize, GEMM_SMEM);
    cudaFuncSetAttribute(gemm_mma<1>, cudaFuncAttributeMaxDynamicSharedMemorySize, GEMM_SMEM);
    cudaFuncSetAttribute(attn_mma, cudaFuncAttributeMaxDynamicSharedMemorySize, ATTN_SMEM);

    split_plain<<<(MROWS * DD / 4 + 255) / 256, 256>>>(x, xhi, xlo, MROWS * DD / 4);
    split_T<<<dim3(N3 / 32, DD / 32), dim3(32, 8)>>>(w_attn, wahi, walo, N3);
    split_T<<<dim3(DD / 32, DD / 32), dim3(32, 8)>>>(w_proj, wphi, wplo, DD);

    gemm_mma<0><<<dim3(N3 / 128, MROWS / 128), 256, GEMM_SMEM>>>(xhi, xlo, wahi, walo, b_attn, out);

    attn_mma<<<dim3(SS / 128, HH, BB), 256, ATTN_SMEM>>>(out);

    gemm_mma<1><<<dim3(DD / 128, MROWS / 128), 256, GEMM_SMEM>>>(ahhi, ahlo, wphi, wplo, b_proj, out);
}

// round 13
// speedup vs baseline: 1.4683x; 1.4683x over previous
#include <cuda_runtime.h>
#include <cuda_fp16.h>
#include <cstdint>

// Problem constants
#define BB 2
#define SS 2048
#define DD 1024
#define HH 16
#define HD 64
#define N3 3072
#define MROWS 4096

// d_out layout
#define A_SZ   ((long long)BB * SS * DD)
#define P_HALF ((long long)BB * HH * SS * HD)
#define P_OFF  (A_SZ)
#define ATTN_OFF (A_SZ + 2 * P_HALF)

#define QKV_N (BB * HH * SS * HD)

// Scratch (device globals) — fp16, A-side 2-digit / B-side single
__device__ __half g_xh[MROWS * DD], g_xl[MROWS * DD];
__device__ __half g_wa[N3 * DD];          // w_attn^T [3072,1024] single digit
__device__ __half g_wp[DD * DD];          // w_proj^T single digit
__device__ __half g_ahh[MROWS * DD], g_ahl[MROWS * DD];
__device__ __half g_q1[QKV_N], g_q2[QKV_N];   // q 2-digit
__device__ __half g_k[QKV_N], g_v[QKV_N];     // k,v single digit

// ====================== base-PTX helpers ====================================
__device__ __forceinline__ uint32_t smem_u32(const void* p) {
    uint32_t a;
    asm("{ .reg .u64 t; cvta.to.shared.u64 t, %1; cvt.u32.u64 %0, t; }"
        : "=r"(a) : "l"(p));
    return a;
}
__device__ __forceinline__ void cpa16(uint32_t s, const void* g) {
    asm volatile("cp.async.cg.shared.global [%0], [%1], 16;" :: "r"(s), "l"(g));
}
#define CP_COMMIT() asm volatile("cp.async.commit_group;" ::: "memory")
#define CP_WAIT(n)  asm volatile("cp.async.wait_group %0;" :: "n"(n) : "memory")

__device__ __forceinline__ void ldsm4(uint32_t* r, uint32_t a) {
    asm volatile("ldmatrix.sync.aligned.m8n8.x4.shared.b16 {%0,%1,%2,%3}, [%4];"
                 : "=r"(r[0]), "=r"(r[1]), "=r"(r[2]), "=r"(r[3]) : "r"(a));
}
__device__ __forceinline__ void ldsm2(uint32_t* r, uint32_t a) {
    asm volatile("ldmatrix.sync.aligned.m8n8.x2.shared.b16 {%0,%1}, [%2];"
                 : "=r"(r[0]), "=r"(r[1]) : "r"(a));
}
__device__ __forceinline__ void ldsm2t(uint32_t* r, uint32_t a) {
    asm volatile("ldmatrix.sync.aligned.m8n8.x2.trans.shared.b16 {%0,%1}, [%2];"
                 : "=r"(r[0]), "=r"(r[1]) : "r"(a));
}
__device__ __forceinline__ void mma_f16(float* d, const uint32_t* a, const uint32_t* b) {
    asm volatile("mma.sync.aligned.m16n8k16.row.col.f32.f16.f16.f32 "
                 "{%0,%1,%2,%3}, {%4,%5,%6,%7}, {%8,%9}, {%0,%1,%2,%3};"
                 : "+f"(d[0]), "+f"(d[1]), "+f"(d[2]), "+f"(d[3])
                 : "r"(a[0]), "r"(a[1]), "r"(a[2]), "r"(a[3]), "r"(b[0]), "r"(b[1]));
}
__device__ __forceinline__ void sp16(float x, uint16_t& h, uint16_t& l) {
    __half hh = __float2half_rn(x);
    h = __half_as_ushort(hh);
    l = __half_as_ushort(__float2half_rn(x - __half2float(hh)));
}
__device__ __forceinline__ uint16_t h16(float x) {
    return __half_as_ushort(__float2half_rn(x));
}
__device__ __forceinline__ uint32_t pk(uint16_t a, uint16_t b) {
    return (uint32_t)a | ((uint32_t)b << 16);
}

// ====================== preprocessing kernels ===============================
// x fp32 -> 2-digit fp16
__global__ __launch_bounds__(256) void split2(const float* __restrict__ in,
                                              __half* __restrict__ hi,
                                              __half* __restrict__ lo, int n4) {
    int i = blockIdx.x * 256 + threadIdx.x;
    if (i >= n4) return;
    float4 v = ((const float4*)in)[i];
    uint16_t h0, h1, h2, h3, l0, l1, l2, l3;
    sp16(v.x, h0, l0); sp16(v.y, h1, l1); sp16(v.z, h2, l2); sp16(v.w, h3, l3);
    ((uint2*)hi)[i] = make_uint2(pk(h0, h1), pk(h2, h3));
    ((uint2*)lo)[i] = make_uint2(pk(l0, l1), pk(l2, l3));
}

// transpose: w fp32 [1024 x N] -> wT fp16 [N x 1024] single digit
__global__ __launch_bounds__(256) void split_T1(const float* __restrict__ in,
                                                __half* __restrict__ o, int N) {
    __shared__ float t[32][33];
    int nb = blockIdx.x * 32, kb = blockIdx.y * 32;
#pragma unroll
    for (int r = 0; r < 4; r++)
        t[threadIdx.y + r * 8][threadIdx.x] =
            in[(long long)(kb + threadIdx.y + r * 8) * N + nb + threadIdx.x];
    __syncthreads();
#pragma unroll
    for (int r = 0; r < 4; r++) {
        int n = nb + threadIdx.y + r * 8;
        float v = t[threadIdx.x][threadIdx.y + r * 8];
        o[(long long)n * 1024 + kb + threadIdx.x] = __float2half_rn(v);
    }
}

// ====================== pipelined mma.sync GEMM (fp16 x2) ===================
// D[128,128] = A[128,1024]@B[N,1024]^T; A 2-digit (Ah,Al), B single.
#define GPB 80
#define GT_TILEB (128 * GPB)           // 10240
#define GT_STAGEB (3 * GT_TILEB)       // 30720
#define GEMM_SMEM (2 * GT_STAGEB)      // 61440

template <int MODE>
__global__ __launch_bounds__(256, 2) void gemm_mma(
    const __half* __restrict__ Ahi, const __half* __restrict__ Alo,
    const __half* __restrict__ B1,
    const float* __restrict__ bias, float* __restrict__ out) {
    extern __shared__ char smm[];
    const uint32_t sb = smem_u32(smm);
    const int tid = threadIdx.x;
    const int lane = tid & 31, warp = tid >> 5;
    const int wm = warp >> 1, wn = warp & 1;
    const int qr = lane >> 2, qc2 = (lane & 3) * 2;
    const int nbase = blockIdx.x * 128, rbase = blockIdx.y * 128;

    float o[2][8][4];
#pragma unroll
    for (int a = 0; a < 2; a++)
#pragma unroll
        for (int b = 0; b < 8; b++)
#pragma unroll
            for (int c = 0; c < 4; c++) o[a][b][c] = 0.f;

    const char* srcs[3] = {
        (const char*)(Ahi + (long long)rbase * 1024),
        (const char*)(Alo + (long long)rbase * 1024),
        (const char*)(B1 + (long long)nbase * 1024)};

    // prologue: stage 0 (3 tiles x 128 rows x 64B = 1536 chunks, 6/thread)
#pragma unroll
    for (int i = 0; i < 6; i++) {
        int idx = tid + i * 256;
        int t = idx >> 9, q = idx & 511, r = q >> 2, c = q & 3;
        cpa16(sb + t * GT_TILEB + r * GPB + c * 16,
              srcs[t] + (long long)r * 2048 + c * 16);
    }
    CP_COMMIT();

    for (int ks = 0; ks < 32; ks++) {
        if (ks + 1 < 32) {
            const int kboff = (ks + 1) * 64;
            const uint32_t dstb = sb + ((ks + 1) & 1) * GT_STAGEB;
#pragma unroll
            for (int i = 0; i < 6; i++) {
                int idx = tid + i * 256;
                int t = idx >> 9, q = idx & 511, r = q >> 2, c = q & 3;
                cpa16(dstb + t * GT_TILEB + r * GPB + c * 16,
                      srcs[t] + (long long)r * 2048 + kboff + c * 16);
            }
            CP_COMMIT();
            CP_WAIT(1);
        } else {
            CP_WAIT(0);
        }
        __syncthreads();

        const uint32_t base = sb + (ks & 1) * GT_STAGEB;
#pragma unroll
        for (int j = 0; j < 2; j++) {       // two k16 slices per 64B chunk
            uint32_t ah[2][4], al[2][4];
#pragma unroll
            for (int mt = 0; mt < 2; mt++) {
                uint32_t r = wm * 32 + mt * 16 + (lane & 7) + ((lane >> 3) & 1) * 8;
                uint32_t cb = j * 32 + (lane >> 4) * 16;
                uint32_t off = r * GPB + cb;
                ldsm4(ah[mt], base + off);
                ldsm4(al[mt], base + GT_TILEB + off);
            }
#pragma unroll
            for (int g = 0; g < 2; g++) {
                uint32_t bf[4][2];
#pragma unroll
                for (int u = 0; u < 4; u++) {
                    int nt = g * 4 + u;
                    uint32_t n = wn * 64 + nt * 8 + (lane & 7);
                    uint32_t cb = j * 32 + ((lane >> 3) & 1) * 16;
                    ldsm2(bf[u], base + 2 * GT_TILEB + n * GPB + cb);
                }
#pragma unroll
                for (int u = 0; u < 4; u++) {
                    mma_f16(o[0][g * 4 + u], ah[0], bf[u]);
                    mma_f16(o[1][g * 4 + u], ah[1], bf[u]);
                }
#pragma unroll
                for (int u = 0; u < 4; u++) {
                    mma_f16(o[0][g * 4 + u], al[0], bf[u]);
                    mma_f16(o[1][g * 4 + u], al[1], bf[u]);
                }
            }
        }
        __syncthreads();
    }

    // epilogue
#pragma unroll
    for (int nt = 0; nt < 8; nt++) {
        const int cg = nbase + wn * 64 + nt * 8 + qc2;
        const float b0 = bias[cg], b1 = bias[cg + 1];
#pragma unroll
        for (int mt = 0; mt < 2; mt++) {
            int r0 = rbase + wm * 32 + mt * 16 + qr;
            int r1 = r0 + 8;
            float2 v0 = make_float2(o[mt][nt][0] + b0, o[mt][nt][1] + b1);
            float2 v1 = make_float2(o[mt][nt][2] + b0, o[mt][nt][3] + b1);
            if (MODE == 0) {
                int which = cg >> 10, d0 = cg & 1023;
                int hh = d0 >> 6, e0 = d0 & 63;
                int b_0 = r0 >> 11, s_0 = r0 & 2047;
                int b_1 = r1 >> 11, s_1 = r1 & 2047;
                long long i0 = (((long long)(b_0 * HH + hh)) * SS + s_0) * HD + e0;
                long long i1 = (((long long)(b_1 * HH + hh)) * SS + s_1) * HD + e0;
                if (which == 0) {
                    uint16_t h0, h1, h2, h3, l0, l1, l2, l3;
                    sp16(v0.x, h0, l0); sp16(v0.y, h1, l1);
                    sp16(v1.x, h2, l2); sp16(v1.y, h3, l3);
                    *(uint32_t*)&g_q1[i0] = pk(h0, h1); *(uint32_t*)&g_q2[i0] = pk(l0, l1);
                    *(uint32_t*)&g_q1[i1] = pk(h2, h3); *(uint32_t*)&g_q2[i1] = pk(l2, l3);
                } else if (which == 1) {
                    *(float2*)&out[P_OFF + i0] = v0;
                    *(float2*)&out[P_OFF + i1] = v1;
                    *(uint32_t*)&g_k[i0] = pk(h16(v0.x), h16(v0.y));
                    *(uint32_t*)&g_k[i1] = pk(h16(v1.x), h16(v1.y));
                } else {
                    *(float2*)&out[P_OFF + P_HALF + i0] = v0;
                    *(float2*)&out[P_OFF + P_HALF + i1] = v1;
                    *(uint32_t*)&g_v[i0] = pk(h16(v0.x), h16(v0.y));
                    *(uint32_t*)&g_v[i1] = pk(h16(v1.x), h16(v1.y));
                }
            } else {
                *(float2*)&out[(long long)r0 * DD + cg] = v0;
                *(float2*)&out[(long long)r1 * DD + cg] = v1;
            }
        }
    }

    // MODE 0: fold in upper-triangle zero-fill of attn region (overlaps with
    // other CTAs' MMA phases; runs before attn_mma in stream order).
    if (MODE == 0) {
        const int cta = blockIdx.y * gridDim.x + blockIdx.x;  // 0..767
        const int bh = cta / 24, sub = cta - bh * 24;
        float* base_a = out + ATTN_OFF + (long long)bh * SS * SS;
        const float4 z = make_float4(0.f, 0.f, 0.f, 0.f);
        // per-bh upper region = sum_qt 128 rows x (15-qt)*32 float4
        for (int oidx = sub * 256 + tid; oidx < 491520; oidx += 24 * 256) {
            int rem = oidx, qt = 0;
            while (qt < 15 && rem >= 4096 * (15 - qt)) { rem -= 4096 * (15 - qt); qt++; }
            int w = (15 - qt) * 32;
            int row = rem / w;
            int c4 = rem - row * w;
            *(float4*)&base_a[(long long)(qt * 128 + row) * SS
                              + (qt + 1) * 128 + c4 * 4] = z;
        }
    }
}

// ====================== attention (2-pass, fp16 x2) =========================
#define APB 144
#define QT_B (128 * APB)               // 18432 per Q digit
#define KT_B (64 * APB)                // 9216 per tile
#define KSTAGE (2 * KT_B)              // 18432: K, V
#define KBASE (2 * QT_B)               // 36864
#define ATTN_SMEM (2 * QT_B + 2 * KSTAGE)   // 73728 -> 2+ CTAs/SM

__global__ __launch_bounds__(256, 2) void attn_mma(float* __restrict__ out) {
    extern __shared__ char smm[];
    const uint32_t sb = smem_u32(smm);
    const int tid = threadIdx.x;
    const int lane = tid & 31, wm = tid >> 5;
    const int qr = lane >> 2, qc2 = (lane & 3) * 2;
    const int qt = (gridDim.x - 1) - blockIdx.x;     // heavy tiles first
    const int h = blockIdx.y, b = blockIdx.z;
    const int qbase = qt * 128;
    const int bh_ = b * HH + h;
    const long long hoff = (long long)bh_ * SS * HD;
    const char* q1g = (const char*)(g_q1 + hoff + (long long)qbase * HD);
    const char* q2g = (const char*)(g_q2 + hoff + (long long)qbase * HD);
    const char* kg = (const char*)(g_k + hoff);
    const char* vg = (const char*)(g_v + hoff);
    float* attn_out = out + ATTN_OFF + (long long)bh_ * SS * SS;
    const int nkt = 2 * qt + 2;

    // load Q digits (each 128 rows x 128B)
#pragma unroll
    for (int i = 0; i < 4; i++) {
        int idx = tid + i * 256;
        int r = idx >> 3, c = idx & 7;
        cpa16(sb + r * APB + c * 16, q1g + idx * 16);
        cpa16(sb + QT_B + r * APB + c * 16, q2g + idx * 16);
    }
    CP_COMMIT();

    // K tile 0 into stage 0
#pragma unroll
    for (int i = 0; i < 2; i++) {
        int idx = tid + i * 256;
        int r = idx >> 3, c = idx & 7;
        cpa16(sb + KBASE + r * APB + c * 16, kg + idx * 16);
    }
    CP_COMMIT();
    CP_WAIT(1);
    __syncthreads();

    uint32_t qh[4][4], ql[4][4];
#pragma unroll
    for (int j = 0; j < 4; j++) {
        uint32_t r = wm * 16 + (lane & 7) + ((lane >> 3) & 1) * 8;
        uint32_t c = j * 16 + (lane >> 4) * 8;
        uint32_t off = r * APB + c * 2;
        ldsm4(qh[j], sb + off);
        ldsm4(ql[j], sb + QT_B + off);
    }

    const int r0g = qbase + wm * 16 + qr;
    const int r1g = r0g + 8;

    // ---------------- pass A: rowsums (K only) ----------------
    float rs0 = 0.f, rs1 = 0.f;
    for (int kt = 0; kt < nkt; kt++) {
        if (kt + 1 < nkt) {
            const uint32_t db = sb + KBASE + ((kt + 1) & 1) * KSTAGE;
            const long long go = (long long)(kt + 1) * 8192;
#pragma unroll
            for (int i = 0; i < 2; i++) {
                int idx = tid + i * 256;
                int r = idx >> 3, c = idx & 7;
                cpa16(db + r * APB + c * 16, kg + go + idx * 16);
            }
            CP_COMMIT();
            CP_WAIT(1);
        } else {
            CP_WAIT(0);
        }
        __syncthreads();

        const uint32_t kb = sb + KBASE + (kt & 1) * KSTAGE;
        float s[8][4];
#pragma unroll
        for (int nt = 0; nt < 8; nt++)
#pragma unroll
            for (int c = 0; c < 4; c++) s[nt][c] = 0.f;

#pragma unroll
        for (int j = 0; j < 4; j++) {
#pragma unroll
            for (int g = 0; g < 2; g++) {
                uint32_t bf[4][2];
#pragma unroll
                for (int u = 0; u < 4; u++) {
                    uint32_t n = (g * 4 + u) * 8 + (lane & 7);
                    uint32_t c = j * 16 + ((lane >> 3) & 1) * 8;
                    ldsm2(bf[u], kb + n * APB + c * 2);
                }
#pragma unroll
                for (int u = 0; u < 4; u++) mma_f16(s[g * 4 + u], qh[j], bf[u]);
#pragma unroll
                for (int u = 0; u < 4; u++) mma_f16(s[g * 4 + u], ql[j], bf[u]);
            }
        }
#pragma unroll
        for (int nt = 0; nt < 8; nt++) {
            const int cg = kt * 64 + nt * 8 + qc2;
            if (cg <= r0g)     rs0 += __expf(s[nt][0] * 0.125f);
            if (cg + 1 <= r0g) rs0 += __expf(s[nt][1] * 0.125f);
            if (cg <= r1g)     rs1 += __expf(s[nt][2] * 0.125f);
            if (cg + 1 <= r1g) rs1 += __expf(s[nt][3] * 0.125f);
        }
        __syncthreads();
    }
    rs0 += __shfl_xor_sync(0xFFFFFFFFu, rs0, 1);
    rs0 += __shfl_xor_sync(0xFFFFFFFFu, rs0, 2);
    rs1 += __shfl_xor_sync(0xFFFFFFFFu, rs1, 1);
    rs1 += __shfl_xor_sync(0xFFFFFFFFu, rs1, 2);
    const float ri0 = 1.0f / rs0;
    const float ri1 = 1.0f / rs1;

    // ---------------- pass B: write attn + A@V ----------------
    float o[8][4];
#pragma unroll
    for (int a = 0; a < 8; a++)
#pragma unroll
        for (int c = 0; c < 4; c++) o[a][c] = 0.f;

    // restart pipeline: K+V tile 0 into stage 0
#pragma unroll
    for (int i = 0; i < 2; i++) {
        int idx = tid + i * 256;
        int r = idx >> 3, c = idx & 7;
        uint32_t db = sb + KBASE;
        cpa16(db + r * APB + c * 16, kg + idx * 16);
        cpa16(db + KT_B + r * APB + c * 16, vg + idx * 16);
    }
    CP_COMMIT();

    for (int kt = 0; kt < nkt; kt++) {
        if (kt + 1 < nkt) {
            const uint32_t db = sb + KBASE + ((kt + 1) & 1) * KSTAGE;
            const long long go = (long long)(kt + 1) * 8192;
#pragma unroll
            for (int i = 0; i < 2; i++) {
                int idx = tid + i * 256;
                int r = idx >> 3, c = idx & 7;
                cpa16(db + r * APB + c * 16, kg + go + idx * 16);
                cpa16(db + KT_B + r * APB + c * 16, vg + go + idx * 16);
            }
            CP_COMMIT();
            CP_WAIT(1);
        } else {
            CP_WAIT(0);
        }
        __syncthreads();

        const uint32_t kb = sb + KBASE + (kt & 1) * KSTAGE;
        float s[8][4];
#pragma unroll
        for (int nt = 0; nt < 8; nt++)
#pragma unroll
            for (int c = 0; c < 4; c++) s[nt][c] = 0.f;
#pragma unroll
        for (int j = 0; j < 4; j++) {
#pragma unroll
            for (int g = 0; g < 2; g++) {
                uint32_t bf[4][2];
#pragma unroll
                for (int u = 0; u < 4; u++) {
                    uint32_t n = (g * 4 + u) * 8 + (lane & 7);
                    uint32_t c = j * 16 + ((lane >> 3) & 1) * 8;
                    ldsm2(bf[u], kb + n * APB + c * 2);
                }
#pragma unroll
                for (int u = 0; u < 4; u++) mma_f16(s[g * 4 + u], qh[j], bf[u]);
#pragma unroll
                for (int u = 0; u < 4; u++) mma_f16(s[g * 4 + u], ql[j], bf[u]);
            }
        }

        // normalized probs -> gmem + fp16 2-digit fragments for AV
        uint32_t pah[4][4], pal[4][4];
#pragma unroll
        for (int nt = 0; nt < 8; nt++) {
            const int cg = kt * 64 + nt * 8 + qc2;
            float e0 = (cg > r0g)     ? 0.f : __expf(s[nt][0] * 0.125f) * ri0;
            float e1 = (cg + 1 > r0g) ? 0.f : __expf(s[nt][1] * 0.125f) * ri0;
            float e2 = (cg > r1g)     ? 0.f : __expf(s[nt][2] * 0.125f) * ri1;
            float e3 = (cg + 1 > r1g) ? 0.f : __expf(s[nt][3] * 0.125f) * ri1;
            *(float2*)&attn_out[(long long)r0g * SS + cg] = make_float2(e0, e1);
            *(float2*)&attn_out[(long long)r1g * SS + cg] = make_float2(e2, e3);
            uint16_t h0, h1, h2, h3, l0, l1, l2, l3;
            sp16(e0, h0, l0); sp16(e1, h1, l1); sp16(e2, h2, l2); sp16(e3, h3, l3);
            const int j = nt >> 1, half = (nt & 1) * 2;
            pah[j][half] = pk(h0, h1); pah[j][half + 1] = pk(h2, h3);
            pal[j][half] = pk(l0, l1); pal[j][half + 1] = pk(l2, l3);
        }
        // A@V (probs 2-digit, V single)
#pragma unroll
        for (int j = 0; j < 4; j++) {
#pragma unroll
            for (int g = 0; g < 2; g++) {
                uint32_t vf[4][2];
#pragma unroll
                for (int u = 0; u < 4; u++) {
                    uint32_t key = j * 16 + ((lane >> 3) & 1) * 8 + (lane & 7);
                    ldsm2t(vf[u], kb + KT_B + key * APB + (g * 4 + u) * 16);
                }
#pragma unroll
                for (int u = 0; u < 4; u++) mma_f16(o[g * 4 + u], pah[j], vf[u]);
#pragma unroll
                for (int u = 0; u < 4; u++) mma_f16(o[g * 4 + u], pal[j], vf[u]);
            }
        }
        __syncthreads();
    }

    // merged-head output as fp16 2-digit (feeds proj GEMM)
#pragma unroll
    for (int nt2 = 0; nt2 < 8; nt2++) {
        const int col = h * 64 + nt2 * 8 + qc2;
        const long long gr0 = (long long)(b * SS + qbase + wm * 16 + qr);
        uint16_t h0, h1, h2, h3, l0, l1, l2, l3;
        sp16(o[nt2][0], h0, l0); sp16(o[nt2][1], h1, l1);
        sp16(o[nt2][2], h2, l2); sp16(o[nt2][3], h3, l3);
        *(uint32_t*)&g_ahh[gr0 * DD + col] = pk(h0, h1);
        *(uint32_t*)&g_ahl[gr0 * DD + col] = pk(l0, l1);
        *(uint32_t*)&g_ahh[(gr0 + 8) * DD + col] = pk(h2, h3);
        *(uint32_t*)&g_ahl[(gr0 + 8) * DD + col] = pk(l2, l3);
    }
}

// ====================== launch ==============================================
extern "C" void kernel_launch(void* const* d_in, const int* in_sizes, int n_in,
                              void* d_out, int out_size) {
    const float* x      = (const float*)d_in[0];
    const float* w_attn = (const float*)d_in[1];
    const float* b_attn = (const float*)d_in[2];
    const float* w_proj = (const float*)d_in[3];
    const float* b_proj = (const float*)d_in[4];
    float* out = (float*)d_out;

    __half *xh, *xl, *wa, *wp, *ahh, *ahl;
    cudaGetSymbolAddress((void**)&xh,  g_xh);
    cudaGetSymbolAddress((void**)&xl,  g_xl);
    cudaGetSymbolAddress((void**)&wa,  g_wa);
    cudaGetSymbolAddress((void**)&wp,  g_wp);
    cudaGetSymbolAddress((void**)&ahh, g_ahh);
    cudaGetSymbolAddress((void**)&ahl, g_ahl);

    cudaFuncSetAttribute(gemm_mma<0>, cudaFuncAttributeMaxDynamicSharedMemorySize, GEMM_SMEM);
    cudaFuncSetAttribute(gemm_mma<1>, cudaFuncAttributeMaxDynamicSharedMemorySize, GEMM_SMEM);
    cudaFuncSetAttribute(attn_mma, cudaFuncAttributeMaxDynamicSharedMemorySize, ATTN_SMEM);

    // 0) prepare fp16 operands
    split2<<<(MROWS * DD / 4 + 255) / 256, 256>>>(x, xh, xl, MROWS * DD / 4);
    split_T1<<<dim3(N3 / 32, DD / 32), dim3(32, 8)>>>(w_attn, wa, N3);
    split_T1<<<dim3(DD / 32, DD / 32), dim3(32, 8)>>>(w_proj, wp, DD);

    // 1) QKV projection (+ upper-triangle zero fill folded in)
    gemm_mma<0><<<dim3(N3 / 128, MROWS / 128), 256, GEMM_SMEM>>>(xh, xl, wa, b_attn, out);

    // 2) attention -> normalized attn region + ah fp16 digits
    attn_mma<<<dim3(SS / 128, HH, BB), 256, ATTN_SMEM>>>(out);

    // 3) output projection
    gemm_mma<1><<<dim3(DD / 128, MROWS / 128), 256, GEMM_SMEM>>>(ahh, ahl, wp, b_proj, out);
}

// round 14
// speedup vs baseline: 1.6192x; 1.1028x over previous
#include <cuda_runtime.h>
#include <cuda_fp16.h>
#include <cstdint>

// Problem constants
#define BB 2
#define SS 2048
#define DD 1024
#define HH 16
#define HD 64
#define N3 3072
#define MROWS 4096

// d_out layout
#define A_SZ   ((long long)BB * SS * DD)
#define P_HALF ((long long)BB * HH * SS * HD)
#define P_OFF  (A_SZ)
#define ATTN_OFF (A_SZ + 2 * P_HALF)

#define QKV_N (BB * HH * SS * HD)

// Scratch (device globals) — fp16, A-side 2-digit / B-side single
__device__ __half g_xh[MROWS * DD], g_xl[MROWS * DD];
__device__ __half g_wa[N3 * DD];          // w_attn^T [3072,1024] single digit
__device__ __half g_wp[DD * DD];          // w_proj^T single digit
__device__ __half g_ahh[MROWS * DD], g_ahl[MROWS * DD];
__device__ __half g_q1[QKV_N], g_q2[QKV_N];   // q 2-digit
__device__ __half g_k[QKV_N], g_v[QKV_N];     // k,v single digit

// ====================== base-PTX helpers ====================================
__device__ __forceinline__ uint32_t smem_u32(const void* p) {
    uint32_t a;
    asm("{ .reg .u64 t; cvta.to.shared.u64 t, %1; cvt.u32.u64 %0, t; }"
        : "=r"(a) : "l"(p));
    return a;
}
__device__ __forceinline__ void cpa16(uint32_t s, const void* g) {
    asm volatile("cp.async.cg.shared.global [%0], [%1], 16;" :: "r"(s), "l"(g));
}
#define CP_COMMIT() asm volatile("cp.async.commit_group;" ::: "memory")
#define CP_WAIT(n)  asm volatile("cp.async.wait_group %0;" :: "n"(n) : "memory")

__device__ __forceinline__ void ldsm4(uint32_t* r, uint32_t a) {
    asm volatile("ldmatrix.sync.aligned.m8n8.x4.shared.b16 {%0,%1,%2,%3}, [%4];"
                 : "=r"(r[0]), "=r"(r[1]), "=r"(r[2]), "=r"(r[3]) : "r"(a));
}
__device__ __forceinline__ void ldsm2(uint32_t* r, uint32_t a) {
    asm volatile("ldmatrix.sync.aligned.m8n8.x2.shared.b16 {%0,%1}, [%2];"
                 : "=r"(r[0]), "=r"(r[1]) : "r"(a));
}
__device__ __forceinline__ void ldsm2t(uint32_t* r, uint32_t a) {
    asm volatile("ldmatrix.sync.aligned.m8n8.x2.trans.shared.b16 {%0,%1}, [%2];"
                 : "=r"(r[0]), "=r"(r[1]) : "r"(a));
}
__device__ __forceinline__ void mma_f16(float* d, const uint32_t* a, const uint32_t* b) {
    asm volatile("mma.sync.aligned.m16n8k16.row.col.f32.f16.f16.f32 "
                 "{%0,%1,%2,%3}, {%4,%5,%6,%7}, {%8,%9}, {%0,%1,%2,%3};"
                 : "+f"(d[0]), "+f"(d[1]), "+f"(d[2]), "+f"(d[3])
                 : "r"(a[0]), "r"(a[1]), "r"(a[2]), "r"(a[3]), "r"(b[0]), "r"(b[1]));
}
__device__ __forceinline__ void sp16(float x, uint16_t& h, uint16_t& l) {
    __half hh = __float2half_rn(x);
    h = __half_as_ushort(hh);
    l = __half_as_ushort(__float2half_rn(x - __half2float(hh)));
}
__device__ __forceinline__ uint16_t h16(float x) {
    return __half_as_ushort(__float2half_rn(x));
}
__device__ __forceinline__ uint32_t pk(uint16_t a, uint16_t b) {
    return (uint32_t)a | ((uint32_t)b << 16);
}

// ====================== preprocessing kernels ===============================
__global__ __launch_bounds__(256) void split2(const float* __restrict__ in,
                                              __half* __restrict__ hi,
                                              __half* __restrict__ lo, int n4) {
    int i = blockIdx.x * 256 + threadIdx.x;
    if (i >= n4) return;
    float4 v = ((const float4*)in)[i];
    uint16_t h0, h1, h2, h3, l0, l1, l2, l3;
    sp16(v.x, h0, l0); sp16(v.y, h1, l1); sp16(v.z, h2, l2); sp16(v.w, h3, l3);
    ((uint2*)hi)[i] = make_uint2(pk(h0, h1), pk(h2, h3));
    ((uint2*)lo)[i] = make_uint2(pk(l0, l1), pk(l2, l3));
}

__global__ __launch_bounds__(256) void split_T1(const float* __restrict__ in,
                                                __half* __restrict__ o, int N) {
    __shared__ float t[32][33];
    int nb = blockIdx.x * 32, kb = blockIdx.y * 32;
#pragma unroll
    for (int r = 0; r < 4; r++)
        t[threadIdx.y + r * 8][threadIdx.x] =
            in[(long long)(kb + threadIdx.y + r * 8) * N + nb + threadIdx.x];
    __syncthreads();
#pragma unroll
    for (int r = 0; r < 4; r++) {
        int n = nb + threadIdx.y + r * 8;
        float v = t[threadIdx.x][threadIdx.y + r * 8];
        o[(long long)n * 1024 + kb + threadIdx.x] = __float2half_rn(v);
    }
}

// upper-triangle zero fill (efficient row-wise indexing)
// grid: (128 rblocks, BB*HH); CTA fills 16 rows of one bh.
__global__ __launch_bounds__(256) void attn_fill(float* __restrict__ out) {
    const int rblock = blockIdx.x, bh = blockIdx.y;
    const int qt = rblock >> 3;          // 128-row tile index
    if (qt >= 15) return;                // last tile has no upper part
    const int w4 = (15 - qt) * 32;       // float4 per row
    const int col0 = (qt + 1) * 128;
    float* base = out + ATTN_OFF + (long long)bh * SS * SS
                  + (long long)rblock * 16 * SS + col0;
    const float4 z = make_float4(0.f, 0.f, 0.f, 0.f);
#pragma unroll 2
    for (int r = 0; r < 16; r++) {
        float4* p = (float4*)&base[(long long)r * SS];
        for (int i = threadIdx.x; i < w4; i += 256) p[i] = z;
    }
}

// ====================== pipelined mma.sync GEMM (fp16 x2) ===================
#define GPB 80
#define GT_TILEB (128 * GPB)           // 10240
#define GT_STAGEB (3 * GT_TILEB)       // 30720
#define GEMM_SMEM (2 * GT_STAGEB)      // 61440

template <int MODE>
__global__ __launch_bounds__(256, 2) void gemm_mma(
    const __half* __restrict__ Ahi, const __half* __restrict__ Alo,
    const __half* __restrict__ B1,
    const float* __restrict__ bias, float* __restrict__ out) {
    extern __shared__ char smm[];
    const uint32_t sb = smem_u32(smm);
    const int tid = threadIdx.x;
    const int lane = tid & 31, warp = tid >> 5;
    const int wm = warp >> 1, wn = warp & 1;
    const int qr = lane >> 2, qc2 = (lane & 3) * 2;
    const int nbase = blockIdx.x * 128, rbase = blockIdx.y * 128;

    float o[2][8][4];
#pragma unroll
    for (int a = 0; a < 2; a++)
#pragma unroll
        for (int b = 0; b < 8; b++)
#pragma unroll
            for (int c = 0; c < 4; c++) o[a][b][c] = 0.f;

    const char* srcs[3] = {
        (const char*)(Ahi + (long long)rbase * 1024),
        (const char*)(Alo + (long long)rbase * 1024),
        (const char*)(B1 + (long long)nbase * 1024)};

    // prologue: stage 0
#pragma unroll
    for (int i = 0; i < 6; i++) {
        int idx = tid + i * 256;
        int t = idx >> 9, q = idx & 511, r = q >> 2, c = q & 3;
        cpa16(sb + t * GT_TILEB + r * GPB + c * 16,
              srcs[t] + (long long)r * 2048 + c * 16);
    }
    CP_COMMIT();

    for (int ks = 0; ks < 32; ks++) {
        if (ks + 1 < 32) {
            const int kboff = (ks + 1) * 64;
            const uint32_t dstb = sb + ((ks + 1) & 1) * GT_STAGEB;
#pragma unroll
            for (int i = 0; i < 6; i++) {
                int idx = tid + i * 256;
                int t = idx >> 9, q = idx & 511, r = q >> 2, c = q & 3;
                cpa16(dstb + t * GT_TILEB + r * GPB + c * 16,
                      srcs[t] + (long long)r * 2048 + kboff + c * 16);
            }
            CP_COMMIT();
            CP_WAIT(1);
        } else {
            CP_WAIT(0);
        }
        __syncthreads();

        const uint32_t base = sb + (ks & 1) * GT_STAGEB;
#pragma unroll
        for (int j = 0; j < 2; j++) {
            uint32_t ah[2][4], al[2][4];
#pragma unroll
            for (int mt = 0; mt < 2; mt++) {
                uint32_t r = wm * 32 + mt * 16 + (lane & 7) + ((lane >> 3) & 1) * 8;
                uint32_t cb = j * 32 + (lane >> 4) * 16;
                uint32_t off = r * GPB + cb;
                ldsm4(ah[mt], base + off);
                ldsm4(al[mt], base + GT_TILEB + off);
            }
#pragma unroll
            for (int g = 0; g < 2; g++) {
                uint32_t bf[4][2];
#pragma unroll
                for (int u = 0; u < 4; u++) {
                    int nt = g * 4 + u;
                    uint32_t n = wn * 64 + nt * 8 + (lane & 7);
                    uint32_t cb = j * 32 + ((lane >> 3) & 1) * 16;
                    ldsm2(bf[u], base + 2 * GT_TILEB + n * GPB + cb);
                }
#pragma unroll
                for (int u = 0; u < 4; u++) {
                    mma_f16(o[0][g * 4 + u], ah[0], bf[u]);
                    mma_f16(o[1][g * 4 + u], ah[1], bf[u]);
                }
#pragma unroll
                for (int u = 0; u < 4; u++) {
                    mma_f16(o[0][g * 4 + u], al[0], bf[u]);
                    mma_f16(o[1][g * 4 + u], al[1], bf[u]);
                }
            }
        }
        __syncthreads();
    }

    // epilogue
#pragma unroll
    for (int nt = 0; nt < 8; nt++) {
        const int cg = nbase + wn * 64 + nt * 8 + qc2;
        const float b0 = bias[cg], b1 = bias[cg + 1];
#pragma unroll
        for (int mt = 0; mt < 2; mt++) {
            int r0 = rbase + wm * 32 + mt * 16 + qr;
            int r1 = r0 + 8;
            float2 v0 = make_float2(o[mt][nt][0] + b0, o[mt][nt][1] + b1);
            float2 v1 = make_float2(o[mt][nt][2] + b0, o[mt][nt][3] + b1);
            if (MODE == 0) {
                int which = cg >> 10, d0 = cg & 1023;
                int hh = d0 >> 6, e0 = d0 & 63;
                int b_0 = r0 >> 11, s_0 = r0 & 2047;
                int b_1 = r1 >> 11, s_1 = r1 & 2047;
                long long i0 = (((long long)(b_0 * HH + hh)) * SS + s_0) * HD + e0;
                long long i1 = (((long long)(b_1 * HH + hh)) * SS + s_1) * HD + e0;
                if (which == 0) {
                    uint16_t h0, h1, h2, h3, l0, l1, l2, l3;
                    sp16(v0.x, h0, l0); sp16(v0.y, h1, l1);
                    sp16(v1.x, h2, l2); sp16(v1.y, h3, l3);
                    *(uint32_t*)&g_q1[i0] = pk(h0, h1); *(uint32_t*)&g_q2[i0] = pk(l0, l1);
                    *(uint32_t*)&g_q1[i1] = pk(h2, h3); *(uint32_t*)&g_q2[i1] = pk(l2, l3);
                } else if (which == 1) {
                    *(float2*)&out[P_OFF + i0] = v0;
                    *(float2*)&out[P_OFF + i1] = v1;
                    *(uint32_t*)&g_k[i0] = pk(h16(v0.x), h16(v0.y));
                    *(uint32_t*)&g_k[i1] = pk(h16(v1.x), h16(v1.y));
                } else {
                    *(float2*)&out[P_OFF + P_HALF + i0] = v0;
                    *(float2*)&out[P_OFF + P_HALF + i1] = v1;
                    *(uint32_t*)&g_v[i0] = pk(h16(v0.x), h16(v0.y));
                    *(uint32_t*)&g_v[i1] = pk(h16(v1.x), h16(v1.y));
                }
            } else {
                *(float2*)&out[(long long)r0 * DD + cg] = v0;
                *(float2*)&out[(long long)r1 * DD + cg] = v1;
            }
        }
    }
}

// ====================== attention (2-pass, fp16 x2) =========================
#define APB 144
#define QT_B (128 * APB)               // 18432 per Q digit
#define KT_B (64 * APB)                // 9216 per tile
#define KSTAGE (2 * KT_B)              // 18432: K, V
#define KBASE (2 * QT_B)               // 36864
#define ATTN_SMEM (2 * QT_B + 2 * KSTAGE)   // 73728

__global__ __launch_bounds__(256, 2) void attn_mma(float* __restrict__ out) {
    extern __shared__ char smm[];
    const uint32_t sb = smem_u32(smm);
    const int tid = threadIdx.x;
    const int lane = tid & 31, wm = tid >> 5;
    const int qr = lane >> 2, qc2 = (lane & 3) * 2;
    const int qt = (gridDim.x - 1) - blockIdx.x;     // heavy tiles first
    const int h = blockIdx.y, b = blockIdx.z;
    const int qbase = qt * 128;
    const int bh_ = b * HH + h;
    const long long hoff = (long long)bh_ * SS * HD;
    const char* q1g = (const char*)(g_q1 + hoff + (long long)qbase * HD);
    const char* q2g = (const char*)(g_q2 + hoff + (long long)qbase * HD);
    const char* kg = (const char*)(g_k + hoff);
    const char* vg = (const char*)(g_v + hoff);
    float* attn_out = out + ATTN_OFF + (long long)bh_ * SS * SS;
    const int nkt = 2 * qt + 2;

    // load Q digits
#pragma unroll
    for (int i = 0; i < 4; i++) {
        int idx = tid + i * 256;
        int r = idx >> 3, c = idx & 7;
        cpa16(sb + r * APB + c * 16, q1g + idx * 16);
        cpa16(sb + QT_B + r * APB + c * 16, q2g + idx * 16);
    }
    CP_COMMIT();

    // K tile 0 into stage 0
#pragma unroll
    for (int i = 0; i < 2; i++) {
        int idx = tid + i * 256;
        int r = idx >> 3, c = idx & 7;
        cpa16(sb + KBASE + r * APB + c * 16, kg + idx * 16);
    }
    CP_COMMIT();
    CP_WAIT(1);
    __syncthreads();

    uint32_t qh[4][4], ql[4][4];
#pragma unroll
    for (int j = 0; j < 4; j++) {
        uint32_t r = wm * 16 + (lane & 7) + ((lane >> 3) & 1) * 8;
        uint32_t c = j * 16 + (lane >> 4) * 8;
        uint32_t off = r * APB + c * 2;
        ldsm4(qh[j], sb + off);
        ldsm4(ql[j], sb + QT_B + off);
    }

    const int r0g = qbase + wm * 16 + qr;
    const int r1g = r0g + 8;

    // ---------------- pass A: rowsums (K only, q single-digit) -------------
    float rs0 = 0.f, rs1 = 0.f;
    for (int kt = 0; kt < nkt; kt++) {
        if (kt + 1 < nkt) {
            const uint32_t db = sb + KBASE + ((kt + 1) & 1) * KSTAGE;
            const long long go = (long long)(kt + 1) * 8192;
#pragma unroll
            for (int i = 0; i < 2; i++) {
                int idx = tid + i * 256;
                int r = idx >> 3, c = idx & 7;
                cpa16(db + r * APB + c * 16, kg + go + idx * 16);
            }
            CP_COMMIT();
            CP_WAIT(1);
        } else {
            CP_WAIT(0);
        }
        __syncthreads();

        const uint32_t kb = sb + KBASE + (kt & 1) * KSTAGE;
        float s[8][4];
#pragma unroll
        for (int nt = 0; nt < 8; nt++)
#pragma unroll
            for (int c = 0; c < 4; c++) s[nt][c] = 0.f;

#pragma unroll
        for (int j = 0; j < 4; j++) {
#pragma unroll
            for (int g = 0; g < 2; g++) {
                uint32_t bf[4][2];
#pragma unroll
                for (int u = 0; u < 4; u++) {
                    uint32_t n = (g * 4 + u) * 8 + (lane & 7);
                    uint32_t c = j * 16 + ((lane >> 3) & 1) * 8;
                    ldsm2(bf[u], kb + n * APB + c * 2);
                }
#pragma unroll
                for (int u = 0; u < 4; u++) mma_f16(s[g * 4 + u], qh[j], bf[u]);
            }
        }
#pragma unroll
        for (int nt = 0; nt < 8; nt++) {
            const int cg = kt * 64 + nt * 8 + qc2;
            if (cg <= r0g)     rs0 += __expf(s[nt][0] * 0.125f);
            if (cg + 1 <= r0g) rs0 += __expf(s[nt][1] * 0.125f);
            if (cg <= r1g)     rs1 += __expf(s[nt][2] * 0.125f);
            if (cg + 1 <= r1g) rs1 += __expf(s[nt][3] * 0.125f);
        }
        __syncthreads();
    }
    rs0 += __shfl_xor_sync(0xFFFFFFFFu, rs0, 1);
    rs0 += __shfl_xor_sync(0xFFFFFFFFu, rs0, 2);
    rs1 += __shfl_xor_sync(0xFFFFFFFFu, rs1, 1);
    rs1 += __shfl_xor_sync(0xFFFFFFFFu, rs1, 2);
    const float ri0 = 1.0f / rs0;
    const float ri1 = 1.0f / rs1;

    // ---------------- pass B: write attn + A@V ----------------
    float o[8][4];
#pragma unroll
    for (int a = 0; a < 8; a++)
#pragma unroll
        for (int c = 0; c < 4; c++) o[a][c] = 0.f;

    // restart pipeline: K+V tile 0 into stage 0
#pragma unroll
    for (int i = 0; i < 2; i++) {
        int idx = tid + i * 256;
        int r = idx >> 3, c = idx & 7;
        uint32_t db = sb + KBASE;
        cpa16(db + r * APB + c * 16, kg + idx * 16);
        cpa16(db + KT_B + r * APB + c * 16, vg + idx * 16);
    }
    CP_COMMIT();

    for (int kt = 0; kt < nkt; kt++) {
        if (kt + 1 < nkt) {
            const uint32_t db = sb + KBASE + ((kt + 1) & 1) * KSTAGE;
            const long long go = (long long)(kt + 1) * 8192;
#pragma unroll
            for (int i = 0; i < 2; i++) {
                int idx = tid + i * 256;
                int r = idx >> 3, c = idx & 7;
                cpa16(db + r * APB + c * 16, kg + go + idx * 16);
                cpa16(db + KT_B + r * APB + c * 16, vg + go + idx * 16);
            }
            CP_COMMIT();
            CP_WAIT(1);
        } else {
            CP_WAIT(0);
        }
        __syncthreads();

        const uint32_t kb = sb + KBASE + (kt & 1) * KSTAGE;
        float s[8][4];
#pragma unroll
        for (int nt = 0; nt < 8; nt++)
#pragma unroll
            for (int c = 0; c < 4; c++) s[nt][c] = 0.f;
#pragma unroll
        for (int j = 0; j < 4; j++) {
#pragma unroll
            for (int g = 0; g < 2; g++) {
                uint32_t bf[4][2];
#pragma unroll
                for (int u = 0; u < 4; u++) {
                    uint32_t n = (g * 4 + u) * 8 + (lane & 7);
                    uint32_t c = j * 16 + ((lane >> 3) & 1) * 8;
                    ldsm2(bf[u], kb + n * APB + c * 2);
                }
#pragma unroll
                for (int u = 0; u < 4; u++) mma_f16(s[g * 4 + u], qh[j], bf[u]);
#pragma unroll
                for (int u = 0; u < 4; u++) mma_f16(s[g * 4 + u], ql[j], bf[u]);
            }
        }

        // normalized probs -> gmem + fp16 2-digit fragments for AV
        uint32_t pah[4][4], pal[4][4];
#pragma unroll
        for (int nt = 0; nt < 8; nt++) {
            const int cg = kt * 64 + nt * 8 + qc2;
            float e0 = (cg > r0g)     ? 0.f : __expf(s[nt][0] * 0.125f) * ri0;
            float e1 = (cg + 1 > r0g) ? 0.f : __expf(s[nt][1] * 0.125f) * ri0;
            float e2 = (cg > r1g)     ? 0.f : __expf(s[nt][2] * 0.125f) * ri1;
            float e3 = (cg + 1 > r1g) ? 0.f : __expf(s[nt][3] * 0.125f) * ri1;
            *(float2*)&attn_out[(long long)r0g * SS + cg] = make_float2(e0, e1);
            *(float2*)&attn_out[(long long)r1g * SS + cg] = make_float2(e2, e3);
            uint16_t h0, h1, h2, h3, l0, l1, l2, l3;
            sp16(e0, h0, l0); sp16(e1, h1, l1); sp16(e2, h2, l2); sp16(e3, h3, l3);
            const int j = nt >> 1, half = (nt & 1) * 2;
            pah[j][half] = pk(h0, h1); pah[j][half + 1] = pk(h2, h3);
            pal[j][half] = pk(l0, l1); pal[j][half + 1] = pk(l2, l3);
        }
        // A@V (probs 2-digit, V single)
#pragma unroll
        for (int j = 0; j < 4; j++) {
#pragma unroll
            for (int g = 0; g < 2; g++) {
                uint32_t vf[4][2];
#pragma unroll
                for (int u = 0; u < 4; u++) {
                    uint32_t key = j * 16 + ((lane >> 3) & 1) * 8 + (lane & 7);
                    ldsm2t(vf[u], kb + KT_B + key * APB + (g * 4 + u) * 16);
                }
#pragma unroll
                for (int u = 0; u < 4; u++) mma_f16(o[g * 4 + u], pah[j], vf[u]);
#pragma unroll
                for (int u = 0; u < 4; u++) mma_f16(o[g * 4 + u], pal[j], vf[u]);
            }
        }
        __syncthreads();
    }

    // merged-head output as fp16 2-digit (feeds proj GEMM)
#pragma unroll
    for (int nt2 = 0; nt2 < 8; nt2++) {
        const int col = h * 64 + nt2 * 8 + qc2;
        const long long gr0 = (long long)(b * SS + qbase + wm * 16 + qr);
        uint16_t h0, h1, h2, h3, l0, l1, l2, l3;
        sp16(o[nt2][0], h0, l0); sp16(o[nt2][1], h1, l1);
        sp16(o[nt2][2], h2, l2); sp16(o[nt2][3], h3, l3);
        *(uint32_t*)&g_ahh[gr0 * DD + col] = pk(h0, h1);
        *(uint32_t*)&g_ahl[gr0 * DD + col] = pk(l0, l1);
        *(uint32_t*)&g_ahh[(gr0 + 8) * DD + col] = pk(h2, h3);
        *(uint32_t*)&g_ahl[(gr0 + 8) * DD + col] = pk(l2, l3);
    }
}

// ====================== launch ==============================================
extern "C" void kernel_launch(void* const* d_in, const int* in_sizes, int n_in,
                              void* d_out, int out_size) {
    const float* x      = (const float*)d_in[0];
    const float* w_attn = (const float*)d_in[1];
    const float* b_attn = (const float*)d_in[2];
    const float* w_proj = (const float*)d_in[3];
    const float* b_proj = (const float*)d_in[4];
    float* out = (float*)d_out;

    __half *xh, *xl, *wa, *wp, *ahh, *ahl;
    cudaGetSymbolAddress((void**)&xh,  g_xh);
    cudaGetSymbolAddress((void**)&xl,  g_xl);
    cudaGetSymbolAddress((void**)&wa,  g_wa);
    cudaGetSymbolAddress((void**)&wp,  g_wp);
    cudaGetSymbolAddress((void**)&ahh, g_ahh);
    cudaGetSymbolAddress((void**)&ahl, g_ahl);

    cudaFuncSetAttribute(gemm_mma<0>, cudaFuncAttributeMaxDynamicSharedMemorySize, GEMM_SMEM);
    cudaFuncSetAttribute(gemm_mma<1>, cudaFuncAttributeMaxDynamicSharedMemorySize, GEMM_SMEM);
    cudaFuncSetAttribute(attn_mma, cudaFuncAttributeMaxDynamicSharedMemorySize, ATTN_SMEM);

    // 0) zero-fill upper triangle (independent) + prepare fp16 operands
    attn_fill<<<dim3(128, BB * HH), 256>>>(out);
    split2<<<(MROWS * DD / 4 + 255) / 256, 256>>>(x, xh, xl, MROWS * DD / 4);
    split_T1<<<dim3(N3 / 32, DD / 32), dim3(32, 8)>>>(w_attn, wa, N3);
    split_T1<<<dim3(DD / 32, DD / 32), dim3(32, 8)>>>(w_proj, wp, DD);

    // 1) QKV projection
    gemm_mma<0><<<dim3(N3 / 128, MROWS / 128), 256, GEMM_SMEM>>>(xh, xl, wa, b_attn, out);

    // 2) attention -> normalized attn region + ah fp16 digits
    attn_mma<<<dim3(SS / 128, HH, BB), 256, ATTN_SMEM>>>(out);

    // 3) output projection
    gemm_mma<1><<<dim3(DD / 128, MROWS / 128), 256, GEMM_SMEM>>>(ahh, ahl, wp, b_proj, out);
}

// round 15
// speedup vs baseline: 1.7394x; 1.0742x over previous
#include <cuda_runtime.h>
#include <cuda_fp16.h>
#include <cstdint>

// Problem constants
#define BB 2
#define SS 2048
#define DD 1024
#define HH 16
#define HD 64
#define N3 3072
#define MROWS 4096

// d_out layout
#define A_SZ   ((long long)BB * SS * DD)
#define P_HALF ((long long)BB * HH * SS * HD)
#define P_OFF  (A_SZ)
#define ATTN_OFF (A_SZ + 2 * P_HALF)

#define QKV_N (BB * HH * SS * HD)

// Scratch (device globals) — fp16
__device__ __half g_xh[MROWS * DD], g_xl[MROWS * DD];
__device__ __half g_wa[N3 * DD];          // w_attn^T [3072,1024]
__device__ __half g_wp[DD * DD];          // w_proj^T
__device__ __half g_ahh[MROWS * DD], g_ahl[MROWS * DD];
__device__ __half g_q1[QKV_N];            // q single digit
__device__ __half g_k[QKV_N], g_v[QKV_N]; // k,v single digit

// ====================== base-PTX helpers ====================================
__device__ __forceinline__ uint32_t smem_u32(const void* p) {
    uint32_t a;
    asm("{ .reg .u64 t; cvta.to.shared.u64 t, %1; cvt.u32.u64 %0, t; }"
        : "=r"(a) : "l"(p));
    return a;
}
__device__ __forceinline__ void cpa16(uint32_t s, const void* g) {
    asm volatile("cp.async.cg.shared.global [%0], [%1], 16;" :: "r"(s), "l"(g));
}
#define CP_COMMIT() asm volatile("cp.async.commit_group;" ::: "memory")
#define CP_WAIT(n)  asm volatile("cp.async.wait_group %0;" :: "n"(n) : "memory")

__device__ __forceinline__ void ldsm4(uint32_t* r, uint32_t a) {
    asm volatile("ldmatrix.sync.aligned.m8n8.x4.shared.b16 {%0,%1,%2,%3}, [%4];"
                 : "=r"(r[0]), "=r"(r[1]), "=r"(r[2]), "=r"(r[3]) : "r"(a));
}
__device__ __forceinline__ void ldsm2(uint32_t* r, uint32_t a) {
    asm volatile("ldmatrix.sync.aligned.m8n8.x2.shared.b16 {%0,%1}, [%2];"
                 : "=r"(r[0]), "=r"(r[1]) : "r"(a));
}
__device__ __forceinline__ void ldsm2t(uint32_t* r, uint32_t a) {
    asm volatile("ldmatrix.sync.aligned.m8n8.x2.trans.shared.b16 {%0,%1}, [%2];"
                 : "=r"(r[0]), "=r"(r[1]) : "r"(a));
}
__device__ __forceinline__ void mma_f16(float* d, const uint32_t* a, const uint32_t* b) {
    asm volatile("mma.sync.aligned.m16n8k16.row.col.f32.f16.f16.f32 "
                 "{%0,%1,%2,%3}, {%4,%5,%6,%7}, {%8,%9}, {%0,%1,%2,%3};"
                 : "+f"(d[0]), "+f"(d[1]), "+f"(d[2]), "+f"(d[3])
                 : "r"(a[0]), "r"(a[1]), "r"(a[2]), "r"(a[3]), "r"(b[0]), "r"(b[1]));
}
__device__ __forceinline__ void sp16(float x, uint16_t& h, uint16_t& l) {
    __half hh = __float2half_rn(x);
    h = __half_as_ushort(hh);
    l = __half_as_ushort(__float2half_rn(x - __half2float(hh)));
}
__device__ __forceinline__ uint16_t h16(float x) {
    return __half_as_ushort(__float2half_rn(x));
}
__device__ __forceinline__ uint32_t pk(uint16_t a, uint16_t b) {
    return (uint32_t)a | ((uint32_t)b << 16);
}

// ====================== preprocessing kernels ===============================
__global__ __launch_bounds__(256) void split2(const float* __restrict__ in,
                                              __half* __restrict__ hi,
                                              __half* __restrict__ lo, int n4) {
    int i = blockIdx.x * 256 + threadIdx.x;
    if (i >= n4) return;
    float4 v = ((const float4*)in)[i];
    uint16_t h0, h1, h2, h3, l0, l1, l2, l3;
    sp16(v.x, h0, l0); sp16(v.y, h1, l1); sp16(v.z, h2, l2); sp16(v.w, h3, l3);
    ((uint2*)hi)[i] = make_uint2(pk(h0, h1), pk(h2, h3));
    ((uint2*)lo)[i] = make_uint2(pk(l0, l1), pk(l2, l3));
}

__global__ __launch_bounds__(256) void split_T1(const float* __restrict__ in,
                                                __half* __restrict__ o, int N) {
    __shared__ float t[32][33];
    int nb = blockIdx.x * 32, kb = blockIdx.y * 32;
#pragma unroll
    for (int r = 0; r < 4; r++)
        t[threadIdx.y + r * 8][threadIdx.x] =
            in[(long long)(kb + threadIdx.y + r * 8) * N + nb + threadIdx.x];
    __syncthreads();
#pragma unroll
    for (int r = 0; r < 4; r++) {
        int n = nb + threadIdx.y + r * 8;
        float v = t[threadIdx.x][threadIdx.y + r * 8];
        o[(long long)n * 1024 + kb + threadIdx.x] = __float2half_rn(v);
    }
}

// upper-triangle zero fill
__global__ __launch_bounds__(256) void attn_fill(float* __restrict__ out) {
    const int rblock = blockIdx.x, bh = blockIdx.y;
    const int qt = rblock >> 3;
    if (qt >= 15) return;
    const int w4 = (15 - qt) * 32;
    const int col0 = (qt + 1) * 128;
    float* base = out + ATTN_OFF + (long long)bh * SS * SS
                  + (long long)rblock * 16 * SS + col0;
    const float4 z = make_float4(0.f, 0.f, 0.f, 0.f);
#pragma unroll 2
    for (int r = 0; r < 16; r++) {
        float4* p = (float4*)&base[(long long)r * SS];
        for (int i = threadIdx.x; i < w4; i += 256) p[i] = z;
    }
}

// ====================== pipelined mma.sync GEMM (fp16 x2) ===================
#define GPB 80
#define GT_TILEB (128 * GPB)           // 10240
#define GT_STAGEB (3 * GT_TILEB)       // 30720
#define GEMM_SMEM (2 * GT_STAGEB)      // 61440

template <int MODE>
__global__ __launch_bounds__(256, 2) void gemm_mma(
    const __half* __restrict__ Ahi, const __half* __restrict__ Alo,
    const __half* __restrict__ B1,
    const float* __restrict__ bias, float* __restrict__ out) {
    extern __shared__ char smm[];
    const uint32_t sb = smem_u32(smm);
    const int tid = threadIdx.x;
    const int lane = tid & 31, warp = tid >> 5;
    const int wm = warp >> 1, wn = warp & 1;
    const int qr = lane >> 2, qc2 = (lane & 3) * 2;
    const int nbase = blockIdx.x * 128, rbase = blockIdx.y * 128;

    float o[2][8][4];
#pragma unroll
    for (int a = 0; a < 2; a++)
#pragma unroll
        for (int b = 0; b < 8; b++)
#pragma unroll
            for (int c = 0; c < 4; c++) o[a][b][c] = 0.f;

    const char* srcs[3] = {
        (const char*)(Ahi + (long long)rbase * 1024),
        (const char*)(Alo + (long long)rbase * 1024),
        (const char*)(B1 + (long long)nbase * 1024)};

    // prologue: stage 0
#pragma unroll
    for (int i = 0; i < 6; i++) {
        int idx = tid + i * 256;
        int t = idx >> 9, q = idx & 511, r = q >> 2, c = q & 3;
        cpa16(sb + t * GT_TILEB + r * GPB + c * 16,
              srcs[t] + (long long)r * 2048 + c * 16);
    }
    CP_COMMIT();

    for (int ks = 0; ks < 32; ks++) {
        if (ks + 1 < 32) {
            const int kboff = (ks + 1) * 64;
            const uint32_t dstb = sb + ((ks + 1) & 1) * GT_STAGEB;
#pragma unroll
            for (int i = 0; i < 6; i++) {
                int idx = tid + i * 256;
                int t = idx >> 9, q = idx & 511, r = q >> 2, c = q & 3;
                cpa16(dstb + t * GT_TILEB + r * GPB + c * 16,
                      srcs[t] + (long long)r * 2048 + kboff + c * 16);
            }
            CP_COMMIT();
            CP_WAIT(1);
        } else {
            CP_WAIT(0);
        }
        __syncthreads();

        const uint32_t base = sb + (ks & 1) * GT_STAGEB;
#pragma unroll
        for (int j = 0; j < 2; j++) {
            uint32_t ah[2][4], al[2][4];
#pragma unroll
            for (int mt = 0; mt < 2; mt++) {
                uint32_t r = wm * 32 + mt * 16 + (lane & 7) + ((lane >> 3) & 1) * 8;
                uint32_t cb = j * 32 + (lane >> 4) * 16;
                uint32_t off = r * GPB + cb;
                ldsm4(ah[mt], base + off);
                ldsm4(al[mt], base + GT_TILEB + off);
            }
#pragma unroll
            for (int g = 0; g < 2; g++) {
                uint32_t bf[4][2];
#pragma unroll
                for (int u = 0; u < 4; u++) {
                    int nt = g * 4 + u;
                    uint32_t n = wn * 64 + nt * 8 + (lane & 7);
                    uint32_t cb = j * 32 + ((lane >> 3) & 1) * 16;
                    ldsm2(bf[u], base + 2 * GT_TILEB + n * GPB + cb);
                }
#pragma unroll
                for (int u = 0; u < 4; u++) {
                    mma_f16(o[0][g * 4 + u], ah[0], bf[u]);
                    mma_f16(o[1][g * 4 + u], ah[1], bf[u]);
                }
#pragma unroll
                for (int u = 0; u < 4; u++) {
                    mma_f16(o[0][g * 4 + u], al[0], bf[u]);
                    mma_f16(o[1][g * 4 + u], al[1], bf[u]);
                }
            }
        }
        __syncthreads();
    }

    // epilogue
#pragma unroll
    for (int nt = 0; nt < 8; nt++) {
        const int cg = nbase + wn * 64 + nt * 8 + qc2;
        const float b0 = bias[cg], b1 = bias[cg + 1];
#pragma unroll
        for (int mt = 0; mt < 2; mt++) {
            int r0 = rbase + wm * 32 + mt * 16 + qr;
            int r1 = r0 + 8;
            float2 v0 = make_float2(o[mt][nt][0] + b0, o[mt][nt][1] + b1);
            float2 v1 = make_float2(o[mt][nt][2] + b0, o[mt][nt][3] + b1);
            if (MODE == 0) {
                int which = cg >> 10, d0 = cg & 1023;
                int hh = d0 >> 6, e0 = d0 & 63;
                int b_0 = r0 >> 11, s_0 = r0 & 2047;
                int b_1 = r1 >> 11, s_1 = r1 & 2047;
                long long i0 = (((long long)(b_0 * HH + hh)) * SS + s_0) * HD + e0;
                long long i1 = (((long long)(b_1 * HH + hh)) * SS + s_1) * HD + e0;
                if (which == 0) {
                    *(uint32_t*)&g_q1[i0] = pk(h16(v0.x), h16(v0.y));
                    *(uint32_t*)&g_q1[i1] = pk(h16(v1.x), h16(v1.y));
                } else if (which == 1) {
                    *(float2*)&out[P_OFF + i0] = v0;
                    *(float2*)&out[P_OFF + i1] = v1;
                    *(uint32_t*)&g_k[i0] = pk(h16(v0.x), h16(v0.y));
                    *(uint32_t*)&g_k[i1] = pk(h16(v1.x), h16(v1.y));
                } else {
                    *(float2*)&out[P_OFF + P_HALF + i0] = v0;
                    *(float2*)&out[P_OFF + P_HALF + i1] = v1;
                    *(uint32_t*)&g_v[i0] = pk(h16(v0.x), h16(v0.y));
                    *(uint32_t*)&g_v[i1] = pk(h16(v1.x), h16(v1.y));
                }
            } else {
                *(float2*)&out[(long long)r0 * DD + cg] = v0;
                *(float2*)&out[(long long)r1 * DD + cg] = v1;
            }
        }
    }
}

// ====================== attention (2-pass, single-digit q/k/v/p) ============
#define APB 144
#define QT_B (128 * APB)               // 18432 (single Q digit)
#define KT_B (64 * APB)                // 9216 per tile
#define KSTAGE (2 * KT_B)              // 18432: K, V
#define KBASE QT_B                     // 18432
#define ATTN_SMEM (QT_B + 2 * KSTAGE)  // 55296

__global__ __launch_bounds__(256, 2) void attn_mma(float* __restrict__ out) {
    extern __shared__ char smm[];
    const uint32_t sb = smem_u32(smm);
    const int tid = threadIdx.x;
    const int lane = tid & 31, wm = tid >> 5;
    const int qr = lane >> 2, qc2 = (lane & 3) * 2;
    const int qt = (gridDim.x - 1) - blockIdx.x;     // heavy tiles first
    const int h = blockIdx.y, b = blockIdx.z;
    const int qbase = qt * 128;
    const int bh_ = b * HH + h;
    const long long hoff = (long long)bh_ * SS * HD;
    const char* q1g = (const char*)(g_q1 + hoff + (long long)qbase * HD);
    const char* kg = (const char*)(g_k + hoff);
    const char* vg = (const char*)(g_v + hoff);
    float* attn_out = out + ATTN_OFF + (long long)bh_ * SS * SS;
    const int nkt = 2 * qt + 2;

    // load Q (single digit, 1024 16B chunks)
#pragma unroll
    for (int i = 0; i < 4; i++) {
        int idx = tid + i * 256;
        int r = idx >> 3, c = idx & 7;
        cpa16(sb + r * APB + c * 16, q1g + idx * 16);
    }
    CP_COMMIT();

    // K tile 0 into stage 0
#pragma unroll
    for (int i = 0; i < 2; i++) {
        int idx = tid + i * 256;
        int r = idx >> 3, c = idx & 7;
        cpa16(sb + KBASE + r * APB + c * 16, kg + idx * 16);
    }
    CP_COMMIT();
    CP_WAIT(1);
    __syncthreads();

    uint32_t qh[4][4];
#pragma unroll
    for (int j = 0; j < 4; j++) {
        uint32_t r = wm * 16 + (lane & 7) + ((lane >> 3) & 1) * 8;
        uint32_t c = j * 16 + (lane >> 4) * 8;
        ldsm4(qh[j], sb + r * APB + c * 2);
    }

    const int r0g = qbase + wm * 16 + qr;
    const int r1g = r0g + 8;

    // ---------------- pass A: rowsums ----------------
    float rs0 = 0.f, rs1 = 0.f;
    for (int kt = 0; kt < nkt; kt++) {
        if (kt + 1 < nkt) {
            const uint32_t db = sb + KBASE + ((kt + 1) & 1) * KSTAGE;
            const long long go = (long long)(kt + 1) * 8192;
#pragma unroll
            for (int i = 0; i < 2; i++) {
                int idx = tid + i * 256;
                int r = idx >> 3, c = idx & 7;
                cpa16(db + r * APB + c * 16, kg + go + idx * 16);
            }
            CP_COMMIT();
            CP_WAIT(1);
        } else {
            CP_WAIT(0);
        }
        __syncthreads();

        const uint32_t kb = sb + KBASE + (kt & 1) * KSTAGE;
        float s[8][4];
#pragma unroll
        for (int nt = 0; nt < 8; nt++)
#pragma unroll
            for (int c = 0; c < 4; c++) s[nt][c] = 0.f;

#pragma unroll
        for (int j = 0; j < 4; j++) {
#pragma unroll
            for (int g = 0; g < 2; g++) {
                uint32_t bf[4][2];
#pragma unroll
                for (int u = 0; u < 4; u++) {
                    uint32_t n = (g * 4 + u) * 8 + (lane & 7);
                    uint32_t c = j * 16 + ((lane >> 3) & 1) * 8;
                    ldsm2(bf[u], kb + n * APB + c * 2);
                }
#pragma unroll
                for (int u = 0; u < 4; u++) mma_f16(s[g * 4 + u], qh[j], bf[u]);
            }
        }
#pragma unroll
        for (int nt = 0; nt < 8; nt++) {
            const int cg = kt * 64 + nt * 8 + qc2;
            if (cg <= r0g)     rs0 += __expf(s[nt][0] * 0.125f);
            if (cg + 1 <= r0g) rs0 += __expf(s[nt][1] * 0.125f);
            if (cg <= r1g)     rs1 += __expf(s[nt][2] * 0.125f);
            if (cg + 1 <= r1g) rs1 += __expf(s[nt][3] * 0.125f);
        }
        __syncthreads();
    }
    rs0 += __shfl_xor_sync(0xFFFFFFFFu, rs0, 1);
    rs0 += __shfl_xor_sync(0xFFFFFFFFu, rs0, 2);
    rs1 += __shfl_xor_sync(0xFFFFFFFFu, rs1, 1);
    rs1 += __shfl_xor_sync(0xFFFFFFFFu, rs1, 2);
    const float ri0 = 1.0f / rs0;
    const float ri1 = 1.0f / rs1;

    // ---------------- pass B: write attn + A@V ----------------
    float o[8][4];
#pragma unroll
    for (int a = 0; a < 8; a++)
#pragma unroll
        for (int c = 0; c < 4; c++) o[a][c] = 0.f;

    // restart pipeline: K+V tile 0 into stage 0
#pragma unroll
    for (int i = 0; i < 2; i++) {
        int idx = tid + i * 256;
        int r = idx >> 3, c = idx & 7;
        uint32_t db = sb + KBASE;
        cpa16(db + r * APB + c * 16, kg + idx * 16);
        cpa16(db + KT_B + r * APB + c * 16, vg + idx * 16);
    }
    CP_COMMIT();

    for (int kt = 0; kt < nkt; kt++) {
        if (kt + 1 < nkt) {
            const uint32_t db = sb + KBASE + ((kt + 1) & 1) * KSTAGE;
            const long long go = (long long)(kt + 1) * 8192;
#pragma unroll
            for (int i = 0; i < 2; i++) {
                int idx = tid + i * 256;
                int r = idx >> 3, c = idx & 7;
                cpa16(db + r * APB + c * 16, kg + go + idx * 16);
                cpa16(db + KT_B + r * APB + c * 16, vg + go + idx * 16);
            }
            CP_COMMIT();
            CP_WAIT(1);
        } else {
            CP_WAIT(0);
        }
        __syncthreads();

        const uint32_t kb = sb + KBASE + (kt & 1) * KSTAGE;
        float s[8][4];
#pragma unroll
        for (int nt = 0; nt < 8; nt++)
#pragma unroll
            for (int c = 0; c < 4; c++) s[nt][c] = 0.f;
#pragma unroll
        for (int j = 0; j < 4; j++) {
#pragma unroll
            for (int g = 0; g < 2; g++) {
                uint32_t bf[4][2];
#pragma unroll
                for (int u = 0; u < 4; u++) {
                    uint32_t n = (g * 4 + u) * 8 + (lane & 7);
                    uint32_t c = j * 16 + ((lane >> 3) & 1) * 8;
                    ldsm2(bf[u], kb + n * APB + c * 2);
                }
#pragma unroll
                for (int u = 0; u < 4; u++) mma_f16(s[g * 4 + u], qh[j], bf[u]);
            }
        }

        // normalized probs -> gmem + single-digit fragments for AV
        uint32_t pah[4][4];
#pragma unroll
        for (int nt = 0; nt < 8; nt++) {
            const int cg = kt * 64 + nt * 8 + qc2;
            float e0 = (cg > r0g)     ? 0.f : __expf(s[nt][0] * 0.125f) * ri0;
            float e1 = (cg + 1 > r0g) ? 0.f : __expf(s[nt][1] * 0.125f) * ri0;
            float e2 = (cg > r1g)     ? 0.f : __expf(s[nt][2] * 0.125f) * ri1;
            float e3 = (cg + 1 > r1g) ? 0.f : __expf(s[nt][3] * 0.125f) * ri1;
            *(float2*)&attn_out[(long long)r0g * SS + cg] = make_float2(e0, e1);
            *(float2*)&attn_out[(long long)r1g * SS + cg] = make_float2(e2, e3);
            const int j = nt >> 1, half = (nt & 1) * 2;
            pah[j][half]     = pk(h16(e0), h16(e1));
            pah[j][half + 1] = pk(h16(e2), h16(e3));
        }
        // A@V (single sweep)
#pragma unroll
        for (int j = 0; j < 4; j++) {
#pragma unroll
            for (int g = 0; g < 2; g++) {
                uint32_t vf[4][2];
#pragma unroll
                for (int u = 0; u < 4; u++) {
                    uint32_t key = j * 16 + ((lane >> 3) & 1) * 8 + (lane & 7);
                    ldsm2t(vf[u], kb + KT_B + key * APB + (g * 4 + u) * 16);
                }
#pragma unroll
                for (int u = 0; u < 4; u++) mma_f16(o[g * 4 + u], pah[j], vf[u]);
            }
        }
        __syncthreads();
    }

    // merged-head output as fp16 2-digit (feeds proj GEMM, keep accurate)
#pragma unroll
    for (int nt2 = 0; nt2 < 8; nt2++) {
        const int col = h * 64 + nt2 * 8 + qc2;
        const long long gr0 = (long long)(b * SS + qbase + wm * 16 + qr);
        uint16_t h0, h1, h2, h3, l0, l1, l2, l3;
        sp16(o[nt2][0], h0, l0); sp16(o[nt2][1], h1, l1);
        sp16(o[nt2][2], h2, l2); sp16(o[nt2][3], h3, l3);
        *(uint32_t*)&g_ahh[gr0 * DD + col] = pk(h0, h1);
        *(uint32_t*)&g_ahl[gr0 * DD + col] = pk(l0, l1);
        *(uint32_t*)&g_ahh[(gr0 + 8) * DD + col] = pk(h2, h3);
        *(uint32_t*)&g_ahl[(gr0 + 8) * DD + col] = pk(l2, l3);
    }
}

// ====================== launch ==============================================
extern "C" void kernel_launch(void* const* d_in, const int* in_sizes, int n_in,
                              void* d_out, int out_size) {
    const float* x      = (const float*)d_in[0];
    const float* w_attn = (const float*)d_in[1];
    const float* b_attn = (const float*)d_in[2];
    const float* w_proj = (const float*)d_in[3];
    const float* b_proj = (const float*)d_in[4];
    float* out = (float*)d_out;

    __half *xh, *xl, *wa, *wp, *ahh, *ahl;
    cudaGetSymbolAddress((void**)&xh,  g_xh);
    cudaGetSymbolAddress((void**)&xl,  g_xl);
    cudaGetSymbolAddress((void**)&wa,  g_wa);
    cudaGetSymbolAddress((void**)&wp,  g_wp);
    cudaGetSymbolAddress((void**)&ahh, g_ahh);
    cudaGetSymbolAddress((void**)&ahl, g_ahl);

    cudaFuncSetAttribute(gemm_mma<0>, cudaFuncAttributeMaxDynamicSharedMemorySize, GEMM_SMEM);
    cudaFuncSetAttribute(gemm_mma<1>, cudaFuncAttributeMaxDynamicSharedMemorySize, GEMM_SMEM);
    cudaFuncSetAttribute(attn_mma, cudaFuncAttributeMaxDynamicSharedMemorySize, ATTN_SMEM);

    // 0) zero-fill upper triangle + prepare fp16 operands
    attn_fill<<<dim3(128, BB * HH), 256>>>(out);
    split2<<<(MROWS * DD / 4 + 255) / 256, 256>>>(x, xh, xl, MROWS * DD / 4);
    split_T1<<<dim3(N3 / 32, DD / 32), dim3(32, 8)>>>(w_attn, wa, N3);
    split_T1<<<dim3(DD / 32, DD / 32), dim3(32, 8)>>>(w_proj, wp, DD);

    // 1) QKV projection
    gemm_mma<0><<<dim3(N3 / 128, MROWS / 128), 256, GEMM_SMEM>>>(xh, xl, wa, b_attn, out);

    // 2) attention -> normalized attn region + ah fp16 digits
    attn_mma<<<dim3(SS / 128, HH, BB), 256, ATTN_SMEM>>>(out);

    // 3) output projection
    gemm_mma<1><<<dim3(DD / 128, MROWS / 128), 256, GEMM_SMEM>>>(ahh, ahl, wp, b_proj, out);
}

// round 16
// speedup vs baseline: 2.0469x; 1.1768x over previous
#include <cuda_runtime.h>
#include <cuda_fp16.h>
#include <cstdint>

// Problem constants
#define BB 2
#define SS 2048
#define DD 1024
#define HH 16
#define HD 64
#define N3 3072
#define MROWS 4096

// d_out layout
#define A_SZ   ((long long)BB * SS * DD)
#define P_HALF ((long long)BB * HH * SS * HD)
#define P_OFF  (A_SZ)
#define ATTN_OFF (A_SZ + 2 * P_HALF)

#define QKV_N (BB * HH * SS * HD)

// Scratch (device globals) — fp16
__device__ __half g_x1[MROWS * DD];       // x single digit
__device__ __half g_wa[N3 * DD];          // w_attn^T [3072,1024]
__device__ __half g_wp[DD * DD];          // w_proj^T
__device__ __half g_ahh[MROWS * DD], g_ahl[MROWS * DD];  // attn out 2-digit
__device__ __half g_q1[QKV_N];            // q single digit
__device__ __half g_k[QKV_N], g_v[QKV_N]; // k,v single digit

// ====================== base-PTX helpers ====================================
__device__ __forceinline__ uint32_t smem_u32(const void* p) {
    uint32_t a;
    asm("{ .reg .u64 t; cvta.to.shared.u64 t, %1; cvt.u32.u64 %0, t; }"
        : "=r"(a) : "l"(p));
    return a;
}
__device__ __forceinline__ void cpa16(uint32_t s, const void* g) {
    asm volatile("cp.async.cg.shared.global [%0], [%1], 16;" :: "r"(s), "l"(g));
}
#define CP_COMMIT() asm volatile("cp.async.commit_group;" ::: "memory")
#define CP_WAIT(n)  asm volatile("cp.async.wait_group %0;" :: "n"(n) : "memory")

__device__ __forceinline__ void ldsm4(uint32_t* r, uint32_t a) {
    asm volatile("ldmatrix.sync.aligned.m8n8.x4.shared.b16 {%0,%1,%2,%3}, [%4];"
                 : "=r"(r[0]), "=r"(r[1]), "=r"(r[2]), "=r"(r[3]) : "r"(a));
}
__device__ __forceinline__ void ldsm2(uint32_t* r, uint32_t a) {
    asm volatile("ldmatrix.sync.aligned.m8n8.x2.shared.b16 {%0,%1}, [%2];"
                 : "=r"(r[0]), "=r"(r[1]) : "r"(a));
}
__device__ __forceinline__ void ldsm2t(uint32_t* r, uint32_t a) {
    asm volatile("ldmatrix.sync.aligned.m8n8.x2.trans.shared.b16 {%0,%1}, [%2];"
                 : "=r"(r[0]), "=r"(r[1]) : "r"(a));
}
__device__ __forceinline__ void mma_f16(float* d, const uint32_t* a, const uint32_t* b) {
    asm volatile("mma.sync.aligned.m16n8k16.row.col.f32.f16.f16.f32 "
                 "{%0,%1,%2,%3}, {%4,%5,%6,%7}, {%8,%9}, {%0,%1,%2,%3};"
                 : "+f"(d[0]), "+f"(d[1]), "+f"(d[2]), "+f"(d[3])
                 : "r"(a[0]), "r"(a[1]), "r"(a[2]), "r"(a[3]), "r"(b[0]), "r"(b[1]));
}
__device__ __forceinline__ void sp16(float x, uint16_t& h, uint16_t& l) {
    __half hh = __float2half_rn(x);
    h = __half_as_ushort(hh);
    l = __half_as_ushort(__float2half_rn(x - __half2float(hh)));
}
__device__ __forceinline__ uint16_t h16(float x) {
    return __half_as_ushort(__float2half_rn(x));
}
__device__ __forceinline__ uint32_t pk(uint16_t a, uint16_t b) {
    return (uint32_t)a | ((uint32_t)b << 16);
}

// ====================== preprocessing kernels ===============================
__global__ __launch_bounds__(256) void split1(const float* __restrict__ in,
                                              __half* __restrict__ hi, int n4) {
    int i = blockIdx.x * 256 + threadIdx.x;
    if (i >= n4) return;
    float4 v = ((const float4*)in)[i];
    ((uint2*)hi)[i] = make_uint2(pk(h16(v.x), h16(v.y)), pk(h16(v.z), h16(v.w)));
}

__global__ __launch_bounds__(256) void split_T1(const float* __restrict__ in,
                                                __half* __restrict__ o, int N) {
    __shared__ float t[32][33];
    int nb = blockIdx.x * 32, kb = blockIdx.y * 32;
#pragma unroll
    for (int r = 0; r < 4; r++)
        t[threadIdx.y + r * 8][threadIdx.x] =
            in[(long long)(kb + threadIdx.y + r * 8) * N + nb + threadIdx.x];
    __syncthreads();
#pragma unroll
    for (int r = 0; r < 4; r++) {
        int n = nb + threadIdx.y + r * 8;
        float v = t[threadIdx.x][threadIdx.y + r * 8];
        o[(long long)n * 1024 + kb + threadIdx.x] = __float2half_rn(v);
    }
}

// upper-triangle zero fill
__global__ __launch_bounds__(256) void attn_fill(float* __restrict__ out) {
    const int rblock = blockIdx.x, bh = blockIdx.y;
    const int qt = rblock >> 3;
    if (qt >= 15) return;
    const int w4 = (15 - qt) * 32;
    const int col0 = (qt + 1) * 128;
    float* base = out + ATTN_OFF + (long long)bh * SS * SS
                  + (long long)rblock * 16 * SS + col0;
    const float4 z = make_float4(0.f, 0.f, 0.f, 0.f);
#pragma unroll 2
    for (int r = 0; r < 16; r++) {
        float4* p = (float4*)&base[(long long)r * SS];
        for (int i = threadIdx.x; i < w4; i += 256) p[i] = z;
    }
}

// ====================== pipelined mma.sync GEMM =============================
// AD = number of A digits (1 or 2). Tiles per stage = AD + 1 (A digits + B).
#define GPB 80
#define GT_TILEB (128 * GPB)           // 10240

template <int MODE, int AD>
__global__ __launch_bounds__(256, 2) void gemm_mma(
    const __half* __restrict__ Ahi, const __half* __restrict__ Alo,
    const __half* __restrict__ B1,
    const float* __restrict__ bias, float* __restrict__ out) {
    constexpr int NTILES = AD + 1;
    constexpr int STAGEB = NTILES * GT_TILEB;
    extern __shared__ char smm[];
    const uint32_t sb = smem_u32(smm);
    const int tid = threadIdx.x;
    const int lane = tid & 31, warp = tid >> 5;
    const int wm = warp >> 1, wn = warp & 1;
    const int qr = lane >> 2, qc2 = (lane & 3) * 2;
    const int nbase = blockIdx.x * 128, rbase = blockIdx.y * 128;

    float o[2][8][4];
#pragma unroll
    for (int a = 0; a < 2; a++)
#pragma unroll
        for (int b = 0; b < 8; b++)
#pragma unroll
            for (int c = 0; c < 4; c++) o[a][b][c] = 0.f;

    const char* srcs[NTILES];
    srcs[0] = (const char*)(Ahi + (long long)rbase * 1024);
    if (AD == 2) srcs[1] = (const char*)(Alo + (long long)rbase * 1024);
    srcs[NTILES - 1 + (AD == 2 ? 1 : 0)] = (const char*)(B1 + (long long)nbase * 1024);
    // (srcs[AD] = B)
    srcs[AD] = (const char*)(B1 + (long long)nbase * 1024);

    // prologue: stage 0 (NTILES x 512 chunks)
#pragma unroll
    for (int i = 0; i < NTILES * 2; i++) {
        int idx = tid + i * 256;
        int t = idx >> 9, q = idx & 511, r = q >> 2, c = q & 3;
        cpa16(sb + t * GT_TILEB + r * GPB + c * 16,
              srcs[t] + (long long)r * 2048 + c * 16);
    }
    CP_COMMIT();

    for (int ks = 0; ks < 32; ks++) {
        if (ks + 1 < 32) {
            const int kboff = (ks + 1) * 64;
            const uint32_t dstb = sb + ((ks + 1) & 1) * STAGEB;
#pragma unroll
            for (int i = 0; i < NTILES * 2; i++) {
                int idx = tid + i * 256;
                int t = idx >> 9, q = idx & 511, r = q >> 2, c = q & 3;
                cpa16(dstb + t * GT_TILEB + r * GPB + c * 16,
                      srcs[t] + (long long)r * 2048 + kboff + c * 16);
            }
            CP_COMMIT();
            CP_WAIT(1);
        } else {
            CP_WAIT(0);
        }
        __syncthreads();

        const uint32_t base = sb + (ks & 1) * STAGEB;
#pragma unroll
        for (int j = 0; j < 2; j++) {
            uint32_t ah[2][4], al[2][4];
#pragma unroll
            for (int mt = 0; mt < 2; mt++) {
                uint32_t r = wm * 32 + mt * 16 + (lane & 7) + ((lane >> 3) & 1) * 8;
                uint32_t cb = j * 32 + (lane >> 4) * 16;
                uint32_t off = r * GPB + cb;
                ldsm4(ah[mt], base + off);
                if (AD == 2) ldsm4(al[mt], base + GT_TILEB + off);
            }
#pragma unroll
            for (int g = 0; g < 2; g++) {
                uint32_t bf[4][2];
#pragma unroll
                for (int u = 0; u < 4; u++) {
                    int nt = g * 4 + u;
                    uint32_t n = wn * 64 + nt * 8 + (lane & 7);
                    uint32_t cb = j * 32 + ((lane >> 3) & 1) * 16;
                    ldsm2(bf[u], base + AD * GT_TILEB + n * GPB + cb);
                }
#pragma unroll
                for (int u = 0; u < 4; u++) {
                    mma_f16(o[0][g * 4 + u], ah[0], bf[u]);
                    mma_f16(o[1][g * 4 + u], ah[1], bf[u]);
                }
                if (AD == 2) {
#pragma unroll
                    for (int u = 0; u < 4; u++) {
                        mma_f16(o[0][g * 4 + u], al[0], bf[u]);
                        mma_f16(o[1][g * 4 + u], al[1], bf[u]);
                    }
                }
            }
        }
        __syncthreads();
    }

    // epilogue
#pragma unroll
    for (int nt = 0; nt < 8; nt++) {
        const int cg = nbase + wn * 64 + nt * 8 + qc2;
        const float b0 = bias[cg], b1 = bias[cg + 1];
#pragma unroll
        for (int mt = 0; mt < 2; mt++) {
            int r0 = rbase + wm * 32 + mt * 16 + qr;
            int r1 = r0 + 8;
            float2 v0 = make_float2(o[mt][nt][0] + b0, o[mt][nt][1] + b1);
            float2 v1 = make_float2(o[mt][nt][2] + b0, o[mt][nt][3] + b1);
            if (MODE == 0) {
                int which = cg >> 10, d0 = cg & 1023;
                int hh = d0 >> 6, e0 = d0 & 63;
                int b_0 = r0 >> 11, s_0 = r0 & 2047;
                int b_1 = r1 >> 11, s_1 = r1 & 2047;
                long long i0 = (((long long)(b_0 * HH + hh)) * SS + s_0) * HD + e0;
                long long i1 = (((long long)(b_1 * HH + hh)) * SS + s_1) * HD + e0;
                if (which == 0) {
                    *(uint32_t*)&g_q1[i0] = pk(h16(v0.x), h16(v0.y));
                    *(uint32_t*)&g_q1[i1] = pk(h16(v1.x), h16(v1.y));
                } else if (which == 1) {
                    *(float2*)&out[P_OFF + i0] = v0;
                    *(float2*)&out[P_OFF + i1] = v1;
                    *(uint32_t*)&g_k[i0] = pk(h16(v0.x), h16(v0.y));
                    *(uint32_t*)&g_k[i1] = pk(h16(v1.x), h16(v1.y));
                } else {
                    *(float2*)&out[P_OFF + P_HALF + i0] = v0;
                    *(float2*)&out[P_OFF + P_HALF + i1] = v1;
                    *(uint32_t*)&g_v[i0] = pk(h16(v0.x), h16(v0.y));
                    *(uint32_t*)&g_v[i1] = pk(h16(v1.x), h16(v1.y));
                }
            } else {
                *(float2*)&out[(long long)r0 * DD + cg] = v0;
                *(float2*)&out[(long long)r1 * DD + cg] = v1;
            }
        }
    }
}

// ====================== attention (2-pass, single-digit q/k/v/p) ============
#define APB 144
#define QT_B (128 * APB)               // 18432 (single Q digit)
#define KT_B (64 * APB)                // 9216 per tile
#define KSTAGE (2 * KT_B)              // 18432: K, V
#define KBASE QT_B                     // 18432
#define ATTN_SMEM (QT_B + 2 * KSTAGE)  // 55296

__global__ __launch_bounds__(256, 2) void attn_mma(float* __restrict__ out) {
    extern __shared__ char smm[];
    const uint32_t sb = smem_u32(smm);
    const int tid = threadIdx.x;
    const int lane = tid & 31, wm = tid >> 5;
    const int qr = lane >> 2, qc2 = (lane & 3) * 2;
    const int qt = (gridDim.x - 1) - blockIdx.x;     // heavy tiles first
    const int h = blockIdx.y, b = blockIdx.z;
    const int qbase = qt * 128;
    const int bh_ = b * HH + h;
    const long long hoff = (long long)bh_ * SS * HD;
    const char* q1g = (const char*)(g_q1 + hoff + (long long)qbase * HD);
    const char* kg = (const char*)(g_k + hoff);
    const char* vg = (const char*)(g_v + hoff);
    float* attn_out = out + ATTN_OFF + (long long)bh_ * SS * SS;
    const int nkt = 2 * qt + 2;

    // load Q (single digit)
#pragma unroll
    for (int i = 0; i < 4; i++) {
        int idx = tid + i * 256;
        int r = idx >> 3, c = idx & 7;
        cpa16(sb + r * APB + c * 16, q1g + idx * 16);
    }
    CP_COMMIT();

    // K tile 0 into stage 0
#pragma unroll
    for (int i = 0; i < 2; i++) {
        int idx = tid + i * 256;
        int r = idx >> 3, c = idx & 7;
        cpa16(sb + KBASE + r * APB + c * 16, kg + idx * 16);
    }
    CP_COMMIT();
    CP_WAIT(1);
    __syncthreads();

    uint32_t qh[4][4];
#pragma unroll
    for (int j = 0; j < 4; j++) {
        uint32_t r = wm * 16 + (lane & 7) + ((lane >> 3) & 1) * 8;
        uint32_t c = j * 16 + (lane >> 4) * 8;
        ldsm4(qh[j], sb + r * APB + c * 2);
    }

    const int r0g = qbase + wm * 16 + qr;
    const int r1g = r0g + 8;

    // ---------------- pass A: rowsums ----------------
    float rs0 = 0.f, rs1 = 0.f;
    for (int kt = 0; kt < nkt; kt++) {
        if (kt + 1 < nkt) {
            const uint32_t db = sb + KBASE + ((kt + 1) & 1) * KSTAGE;
            const long long go = (long long)(kt + 1) * 8192;
#pragma unroll
            for (int i = 0; i < 2; i++) {
                int idx = tid + i * 256;
                int r = idx >> 3, c = idx & 7;
                cpa16(db + r * APB + c * 16, kg + go + idx * 16);
            }
            CP_COMMIT();
            CP_WAIT(1);
        } else {
            CP_WAIT(0);
        }
        __syncthreads();

        const uint32_t kb = sb + KBASE + (kt & 1) * KSTAGE;
        float s[8][4];
#pragma unroll
        for (int nt = 0; nt < 8; nt++)
#pragma unroll
            for (int c = 0; c < 4; c++) s[nt][c] = 0.f;

#pragma unroll
        for (int j = 0; j < 4; j++) {
#pragma unroll
            for (int g = 0; g < 2; g++) {
                uint32_t bf[4][2];
#pragma unroll
                for (int u = 0; u < 4; u++) {
                    uint32_t n = (g * 4 + u) * 8 + (lane & 7);
                    uint32_t c = j * 16 + ((lane >> 3) & 1) * 8;
                    ldsm2(bf[u], kb + n * APB + c * 2);
                }
#pragma unroll
                for (int u = 0; u < 4; u++) mma_f16(s[g * 4 + u], qh[j], bf[u]);
            }
        }
#pragma unroll
        for (int nt = 0; nt < 8; nt++) {
            const int cg = kt * 64 + nt * 8 + qc2;
            if (cg <= r0g)     rs0 += __expf(s[nt][0] * 0.125f);
            if (cg + 1 <= r0g) rs0 += __expf(s[nt][1] * 0.125f);
            if (cg <= r1g)     rs1 += __expf(s[nt][2] * 0.125f);
            if (cg + 1 <= r1g) rs1 += __expf(s[nt][3] * 0.125f);
        }
        __syncthreads();
    }
    rs0 += __shfl_xor_sync(0xFFFFFFFFu, rs0, 1);
    rs0 += __shfl_xor_sync(0xFFFFFFFFu, rs0, 2);
    rs1 += __shfl_xor_sync(0xFFFFFFFFu, rs1, 1);
    rs1 += __shfl_xor_sync(0xFFFFFFFFu, rs1, 2);
    const float ri0 = 1.0f / rs0;
    const float ri1 = 1.0f / rs1;

    // ---------------- pass B: write attn + A@V ----------------
    float o[8][4];
#pragma unroll
    for (int a = 0; a < 8; a++)
#pragma unroll
        for (int c = 0; c < 4; c++) o[a][c] = 0.f;

    // restart pipeline: K+V tile 0 into stage 0
#pragma unroll
    for (int i = 0; i < 2; i++) {
        int idx = tid + i * 256;
        int r = idx >> 3, c = idx & 7;
        uint32_t db = sb + KBASE;
        cpa16(db + r * APB + c * 16, kg + idx * 16);
        cpa16(db + KT_B + r * APB + c * 16, vg + idx * 16);
    }
    CP_COMMIT();

    for (int kt = 0; kt < nkt; kt++) {
        if (kt + 1 < nkt) {
            const uint32_t db = sb + KBASE + ((kt + 1) & 1) * KSTAGE;
            const long long go = (long long)(kt + 1) * 8192;
#pragma unroll
            for (int i = 0; i < 2; i++) {
                int idx = tid + i * 256;
                int r = idx >> 3, c = idx & 7;
                cpa16(db + r * APB + c * 16, kg + go + idx * 16);
                cpa16(db + KT_B + r * APB + c * 16, vg + go + idx * 16);
            }
            CP_COMMIT();
            CP_WAIT(1);
        } else {
            CP_WAIT(0);
        }
        __syncthreads();

        const uint32_t kb = sb + KBASE + (kt & 1) * KSTAGE;
        float s[8][4];
#pragma unroll
        for (int nt = 0; nt < 8; nt++)
#pragma unroll
            for (int c = 0; c < 4; c++) s[nt][c] = 0.f;
#pragma unroll
        for (int j = 0; j < 4; j++) {
#pragma unroll
            for (int g = 0; g < 2; g++) {
                uint32_t bf[4][2];
#pragma unroll
                for (int u = 0; u < 4; u++) {
                    uint32_t n = (g * 4 + u) * 8 + (lane & 7);
                    uint32_t c = j * 16 + ((lane >> 3) & 1) * 8;
                    ldsm2(bf[u], kb + n * APB + c * 2);
                }
#pragma unroll
                for (int u = 0; u < 4; u++) mma_f16(s[g * 4 + u], qh[j], bf[u]);
            }
        }

        // normalized probs -> gmem + single-digit fragments for AV
        uint32_t pah[4][4];
#pragma unroll
        for (int nt = 0; nt < 8; nt++) {
            const int cg = kt * 64 + nt * 8 + qc2;
            float e0 = (cg > r0g)     ? 0.f : __expf(s[nt][0] * 0.125f) * ri0;
            float e1 = (cg + 1 > r0g) ? 0.f : __expf(s[nt][1] * 0.125f) * ri0;
            float e2 = (cg > r1g)     ? 0.f : __expf(s[nt][2] * 0.125f) * ri1;
            float e3 = (cg + 1 > r1g) ? 0.f : __expf(s[nt][3] * 0.125f) * ri1;
            *(float2*)&attn_out[(long long)r0g * SS + cg] = make_float2(e0, e1);
            *(float2*)&attn_out[(long long)r1g * SS + cg] = make_float2(e2, e3);
            const int j = nt >> 1, half = (nt & 1) * 2;
            pah[j][half]     = pk(h16(e0), h16(e1));
            pah[j][half + 1] = pk(h16(e2), h16(e3));
        }
        // A@V (single sweep)
#pragma unroll
        for (int j = 0; j < 4; j++) {
#pragma unroll
            for (int g = 0; g < 2; g++) {
                uint32_t vf[4][2];
#pragma unroll
                for (int u = 0; u < 4; u++) {
                    uint32_t key = j * 16 + ((lane >> 3) & 1) * 8 + (lane & 7);
                    ldsm2t(vf[u], kb + KT_B + key * APB + (g * 4 + u) * 16);
                }
#pragma unroll
                for (int u = 0; u < 4; u++) mma_f16(o[g * 4 + u], pah[j], vf[u]);
            }
        }
        __syncthreads();
    }

    // merged-head output as fp16 2-digit (feeds proj GEMM, keep accurate)
#pragma unroll
    for (int nt2 = 0; nt2 < 8; nt2++) {
        const int col = h * 64 + nt2 * 8 + qc2;
        const long long gr0 = (long long)(b * SS + qbase + wm * 16 + qr);
        uint16_t h0, h1, h2, h3, l0, l1, l2, l3;
        sp16(o[nt2][0], h0, l0); sp16(o[nt2][1], h1, l1);
        sp16(o[nt2][2], h2, l2); sp16(o[nt2][3], h3, l3);
        *(uint32_t*)&g_ahh[gr0 * DD + col] = pk(h0, h1);
        *(uint32_t*)&g_ahl[gr0 * DD + col] = pk(l0, l1);
        *(uint32_t*)&g_ahh[(gr0 + 8) * DD + col] = pk(h2, h3);
        *(uint32_t*)&g_ahl[(gr0 + 8) * DD + col] = pk(l2, l3);
    }
}

// ====================== launch ==============================================
extern "C" void kernel_launch(void* const* d_in, const int* in_sizes, int n_in,
                              void* d_out, int out_size) {
    const float* x      = (const float*)d_in[0];
    const float* w_attn = (const float*)d_in[1];
    const float* b_attn = (const float*)d_in[2];
    const float* w_proj = (const float*)d_in[3];
    const float* b_proj = (const float*)d_in[4];
    float* out = (float*)d_out;

    __half *x1, *wa, *wp, *ahh, *ahl;
    cudaGetSymbolAddress((void**)&x1,  g_x1);
    cudaGetSymbolAddress((void**)&wa,  g_wa);
    cudaGetSymbolAddress((void**)&wp,  g_wp);
    cudaGetSymbolAddress((void**)&ahh, g_ahh);
    cudaGetSymbolAddress((void**)&ahl, g_ahl);

    cudaFuncSetAttribute((const void*)gemm_mma<0, 1>,
                         cudaFuncAttributeMaxDynamicSharedMemorySize, 2 * 2 * GT_TILEB);
    cudaFuncSetAttribute((const void*)gemm_mma<1, 2>,
                         cudaFuncAttributeMaxDynamicSharedMemorySize, 2 * 3 * GT_TILEB);
    cudaFuncSetAttribute(attn_mma, cudaFuncAttributeMaxDynamicSharedMemorySize, ATTN_SMEM);

    // 0) zero-fill upper triangle + prepare fp16 operands
    attn_fill<<<dim3(128, BB * HH), 256>>>(out);
    split1<<<(MROWS * DD / 4 + 255) / 256, 256>>>(x, x1, MROWS * DD / 4);
    split_T1<<<dim3(N3 / 32, DD / 32), dim3(32, 8)>>>(w_attn, wa, N3);
    split_T1<<<dim3(DD / 32, DD / 32), dim3(32, 8)>>>(w_proj, wp, DD);

    // 1) QKV projection (single-digit x)
    gemm_mma<0, 1><<<dim3(N3 / 128, MROWS / 128), 256, 2 * 2 * GT_TILEB>>>(
        x1, nullptr, wa, b_attn, out);

    // 2) attention -> normalized attn region + ah fp16 digits
    attn_mma<<<dim3(SS / 128, HH, BB), 256, ATTN_SMEM>>>(out);

    // 3) output projection (2-digit ah)
    gemm_mma<1, 2><<<dim3(DD / 128, MROWS / 128), 256, 2 * 3 * GT_TILEB>>>(
        ahh, ahl, wp, b_proj, out);
}

// round 17
// speedup vs baseline: 2.1707x; 1.0605x over previous
#include <cuda_runtime.h>
#include <cuda_fp16.h>
#include <cstdint>

// Problem constants
#define BB 2
#define SS 2048
#define DD 1024
#define HH 16
#define HD 64
#define N3 3072
#define MROWS 4096

// d_out layout
#define A_SZ   ((long long)BB * SS * DD)
#define P_HALF ((long long)BB * HH * SS * HD)
#define P_OFF  (A_SZ)
#define ATTN_OFF (A_SZ + 2 * P_HALF)

#define QKV_N (BB * HH * SS * HD)

// Scratch (device globals) — fp16, all single digit
__device__ __half g_x1[MROWS * DD];
__device__ __half g_wa[N3 * DD];          // w_attn^T [3072,1024]
__device__ __half g_wp[DD * DD];          // w_proj^T
__device__ __half g_ah1[MROWS * DD];      // attn merged-head output
__device__ __half g_q1[QKV_N];
__device__ __half g_k[QKV_N], g_v[QKV_N];

// ====================== base-PTX helpers ====================================
__device__ __forceinline__ uint32_t smem_u32(const void* p) {
    uint32_t a;
    asm("{ .reg .u64 t; cvta.to.shared.u64 t, %1; cvt.u32.u64 %0, t; }"
        : "=r"(a) : "l"(p));
    return a;
}
__device__ __forceinline__ void cpa16(uint32_t s, const void* g) {
    asm volatile("cp.async.cg.shared.global [%0], [%1], 16;" :: "r"(s), "l"(g));
}
#define CP_COMMIT() asm volatile("cp.async.commit_group;" ::: "memory")
#define CP_WAIT(n)  asm volatile("cp.async.wait_group %0;" :: "n"(n) : "memory")

__device__ __forceinline__ void ldsm4(uint32_t* r, uint32_t a) {
    asm volatile("ldmatrix.sync.aligned.m8n8.x4.shared.b16 {%0,%1,%2,%3}, [%4];"
                 : "=r"(r[0]), "=r"(r[1]), "=r"(r[2]), "=r"(r[3]) : "r"(a));
}
__device__ __forceinline__ void ldsm2(uint32_t* r, uint32_t a) {
    asm volatile("ldmatrix.sync.aligned.m8n8.x2.shared.b16 {%0,%1}, [%2];"
                 : "=r"(r[0]), "=r"(r[1]) : "r"(a));
}
__device__ __forceinline__ void ldsm2t(uint32_t* r, uint32_t a) {
    asm volatile("ldmatrix.sync.aligned.m8n8.x2.trans.shared.b16 {%0,%1}, [%2];"
                 : "=r"(r[0]), "=r"(r[1]) : "r"(a));
}
__device__ __forceinline__ void mma_f16(float* d, const uint32_t* a, const uint32_t* b) {
    asm volatile("mma.sync.aligned.m16n8k16.row.col.f32.f16.f16.f32 "
                 "{%0,%1,%2,%3}, {%4,%5,%6,%7}, {%8,%9}, {%0,%1,%2,%3};"
                 : "+f"(d[0]), "+f"(d[1]), "+f"(d[2]), "+f"(d[3])
                 : "r"(a[0]), "r"(a[1]), "r"(a[2]), "r"(a[3]), "r"(b[0]), "r"(b[1]));
}
__device__ __forceinline__ uint16_t h16(float x) {
    return __half_as_ushort(__float2half_rn(x));
}
__device__ __forceinline__ uint32_t pk(uint16_t a, uint16_t b) {
    return (uint32_t)a | ((uint32_t)b << 16);
}

// ====================== preprocessing kernels ===============================
__global__ __launch_bounds__(256) void split1(const float* __restrict__ in,
                                              __half* __restrict__ hi, int n4) {
    int i = blockIdx.x * 256 + threadIdx.x;
    if (i >= n4) return;
    float4 v = ((const float4*)in)[i];
    ((uint2*)hi)[i] = make_uint2(pk(h16(v.x), h16(v.y)), pk(h16(v.z), h16(v.w)));
}

__global__ __launch_bounds__(256) void split_T1(const float* __restrict__ in,
                                                __half* __restrict__ o, int N) {
    __shared__ float t[32][33];
    int nb = blockIdx.x * 32, kb = blockIdx.y * 32;
#pragma unroll
    for (int r = 0; r < 4; r++)
        t[threadIdx.y + r * 8][threadIdx.x] =
            in[(long long)(kb + threadIdx.y + r * 8) * N + nb + threadIdx.x];
    __syncthreads();
#pragma unroll
    for (int r = 0; r < 4; r++) {
        int n = nb + threadIdx.y + r * 8;
        float v = t[threadIdx.x][threadIdx.y + r * 8];
        o[(long long)n * 1024 + kb + threadIdx.x] = __float2half_rn(v);
    }
}

// ====================== pipelined mma.sync GEMM (single fp16) ===============
#define GPB 80
#define GT_TILEB (128 * GPB)           // 10240
#define GT_STAGEB (2 * GT_TILEB)       // 20480
#define GEMM_SMEM (2 * GT_STAGEB)      // 40960

template <int MODE>
__global__ __launch_bounds__(256, 2) void gemm_mma(
    const __half* __restrict__ A1, const __half* __restrict__ B1,
    const float* __restrict__ bias, float* __restrict__ out) {
    extern __shared__ char smm[];
    const uint32_t sb = smem_u32(smm);
    const int tid = threadIdx.x;
    const int lane = tid & 31, warp = tid >> 5;
    const int wm = warp >> 1, wn = warp & 1;
    const int qr = lane >> 2, qc2 = (lane & 3) * 2;
    const int nbase = blockIdx.x * 128, rbase = blockIdx.y * 128;

    float o[2][8][4];
#pragma unroll
    for (int a = 0; a < 2; a++)
#pragma unroll
        for (int b = 0; b < 8; b++)
#pragma unroll
            for (int c = 0; c < 4; c++) o[a][b][c] = 0.f;

    const char* srcs[2] = {
        (const char*)(A1 + (long long)rbase * 1024),
        (const char*)(B1 + (long long)nbase * 1024)};

    // prologue: stage 0 (2 tiles x 512 chunks)
#pragma unroll
    for (int i = 0; i < 4; i++) {
        int idx = tid + i * 256;
        int t = idx >> 9, q = idx & 511, r = q >> 2, c = q & 3;
        cpa16(sb + t * GT_TILEB + r * GPB + c * 16,
              srcs[t] + (long long)r * 2048 + c * 16);
    }
    CP_COMMIT();

    for (int ks = 0; ks < 32; ks++) {
        if (ks + 1 < 32) {
            const int kboff = (ks + 1) * 64;
            const uint32_t dstb = sb + ((ks + 1) & 1) * GT_STAGEB;
#pragma unroll
            for (int i = 0; i < 4; i++) {
                int idx = tid + i * 256;
                int t = idx >> 9, q = idx & 511, r = q >> 2, c = q & 3;
                cpa16(dstb + t * GT_TILEB + r * GPB + c * 16,
                      srcs[t] + (long long)r * 2048 + kboff + c * 16);
            }
            CP_COMMIT();
            CP_WAIT(1);
        } else {
            CP_WAIT(0);
        }
        __syncthreads();

        const uint32_t base = sb + (ks & 1) * GT_STAGEB;
#pragma unroll
        for (int j = 0; j < 2; j++) {
            uint32_t ah[2][4];
#pragma unroll
            for (int mt = 0; mt < 2; mt++) {
                uint32_t r = wm * 32 + mt * 16 + (lane & 7) + ((lane >> 3) & 1) * 8;
                uint32_t cb = j * 32 + (lane >> 4) * 16;
                ldsm4(ah[mt], base + r * GPB + cb);
            }
#pragma unroll
            for (int g = 0; g < 2; g++) {
                uint32_t bf[4][2];
#pragma unroll
                for (int u = 0; u < 4; u++) {
                    int nt = g * 4 + u;
                    uint32_t n = wn * 64 + nt * 8 + (lane & 7);
                    uint32_t cb = j * 32 + ((lane >> 3) & 1) * 16;
                    ldsm2(bf[u], base + GT_TILEB + n * GPB + cb);
                }
#pragma unroll
                for (int u = 0; u < 4; u++) {
                    mma_f16(o[0][g * 4 + u], ah[0], bf[u]);
                    mma_f16(o[1][g * 4 + u], ah[1], bf[u]);
                }
            }
        }
        __syncthreads();
    }

    // epilogue
#pragma unroll
    for (int nt = 0; nt < 8; nt++) {
        const int cg = nbase + wn * 64 + nt * 8 + qc2;
        const float b0 = bias[cg], b1 = bias[cg + 1];
#pragma unroll
        for (int mt = 0; mt < 2; mt++) {
            int r0 = rbase + wm * 32 + mt * 16 + qr;
            int r1 = r0 + 8;
            float2 v0 = make_float2(o[mt][nt][0] + b0, o[mt][nt][1] + b1);
            float2 v1 = make_float2(o[mt][nt][2] + b0, o[mt][nt][3] + b1);
            if (MODE == 0) {
                int which = cg >> 10, d0 = cg & 1023;
                int hh = d0 >> 6, e0 = d0 & 63;
                int b_0 = r0 >> 11, s_0 = r0 & 2047;
                int b_1 = r1 >> 11, s_1 = r1 & 2047;
                long long i0 = (((long long)(b_0 * HH + hh)) * SS + s_0) * HD + e0;
                long long i1 = (((long long)(b_1 * HH + hh)) * SS + s_1) * HD + e0;
                if (which == 0) {
                    *(uint32_t*)&g_q1[i0] = pk(h16(v0.x), h16(v0.y));
                    *(uint32_t*)&g_q1[i1] = pk(h16(v1.x), h16(v1.y));
                } else if (which == 1) {
                    *(float2*)&out[P_OFF + i0] = v0;
                    *(float2*)&out[P_OFF + i1] = v1;
                    *(uint32_t*)&g_k[i0] = pk(h16(v0.x), h16(v0.y));
                    *(uint32_t*)&g_k[i1] = pk(h16(v1.x), h16(v1.y));
                } else {
                    *(float2*)&out[P_OFF + P_HALF + i0] = v0;
                    *(float2*)&out[P_OFF + P_HALF + i1] = v1;
                    *(uint32_t*)&g_v[i0] = pk(h16(v0.x), h16(v0.y));
                    *(uint32_t*)&g_v[i1] = pk(h16(v1.x), h16(v1.y));
                }
            } else {
                *(float2*)&out[(long long)r0 * DD + cg] = v0;
                *(float2*)&out[(long long)r1 * DD + cg] = v1;
            }
        }
    }
}

// ====================== attention (2-pass, all single fp16) =================
#define APB 144
#define QT_B (128 * APB)               // 18432
#define KT_B (64 * APB)                // 9216 per tile
#define KSTAGE (2 * KT_B)              // 18432: K, V
#define KBASE QT_B
#define ATTN_SMEM (QT_B + 2 * KSTAGE)  // 55296

__global__ __launch_bounds__(256, 2) void attn_mma(float* __restrict__ out) {
    extern __shared__ char smm[];
    const uint32_t sb = smem_u32(smm);
    const int tid = threadIdx.x;
    const int lane = tid & 31, wm = tid >> 5;
    const int qr = lane >> 2, qc2 = (lane & 3) * 2;
    const int qt = (gridDim.x - 1) - blockIdx.x;     // heavy tiles first
    const int h = blockIdx.y, b = blockIdx.z;
    const int qbase = qt * 128;
    const int bh_ = b * HH + h;
    const long long hoff = (long long)bh_ * SS * HD;
    const char* q1g = (const char*)(g_q1 + hoff + (long long)qbase * HD);
    const char* kg = (const char*)(g_k + hoff);
    const char* vg = (const char*)(g_v + hoff);
    float* attn_out = out + ATTN_OFF + (long long)bh_ * SS * SS;
    const int nkt = 2 * qt + 2;

    // issue Q load
#pragma unroll
    for (int i = 0; i < 4; i++) {
        int idx = tid + i * 256;
        int r = idx >> 3, c = idx & 7;
        cpa16(sb + r * APB + c * 16, q1g + idx * 16);
    }
    CP_COMMIT();

    // issue K tile 0
#pragma unroll
    for (int i = 0; i < 2; i++) {
        int idx = tid + i * 256;
        int r = idx >> 3, c = idx & 7;
        cpa16(sb + KBASE + r * APB + c * 16, kg + idx * 16);
    }
    CP_COMMIT();

    // zero-fill this CTA's upper-triangle strip (overlaps the loads above;
    // fire-and-forget stores, disjoint from all prob writes)
    {
        const int Lc = (qt + 1) * 128;
        if (Lc < SS) {
            const int w4 = (SS - Lc) >> 2;
            const float4 z = make_float4(0.f, 0.f, 0.f, 0.f);
            for (int r = 0; r < 128; r++) {
                float4* p = (float4*)&attn_out[(long long)(qbase + r) * SS + Lc];
                for (int i = tid; i < w4; i += 256) p[i] = z;
            }
        }
    }
    CP_WAIT(1);
    __syncthreads();

    uint32_t qh[4][4];
#pragma unroll
    for (int j = 0; j < 4; j++) {
        uint32_t r = wm * 16 + (lane & 7) + ((lane >> 3) & 1) * 8;
        uint32_t c = j * 16 + (lane >> 4) * 8;
        ldsm4(qh[j], sb + r * APB + c * 2);
    }

    const int r0g = qbase + wm * 16 + qr;
    const int r1g = r0g + 8;

    // ---------------- pass A: rowsums ----------------
    float rs0 = 0.f, rs1 = 0.f;
    for (int kt = 0; kt < nkt; kt++) {
        if (kt + 1 < nkt) {
            const uint32_t db = sb + KBASE + ((kt + 1) & 1) * KSTAGE;
            const long long go = (long long)(kt + 1) * 8192;
#pragma unroll
            for (int i = 0; i < 2; i++) {
                int idx = tid + i * 256;
                int r = idx >> 3, c = idx & 7;
                cpa16(db + r * APB + c * 16, kg + go + idx * 16);
            }
            CP_COMMIT();
            CP_WAIT(1);
        } else {
            CP_WAIT(0);
        }
        __syncthreads();

        const uint32_t kb = sb + KBASE + (kt & 1) * KSTAGE;
        float s[8][4];
#pragma unroll
        for (int nt = 0; nt < 8; nt++)
#pragma unroll
            for (int c = 0; c < 4; c++) s[nt][c] = 0.f;

#pragma unroll
        for (int j = 0; j < 4; j++) {
#pragma unroll
            for (int g = 0; g < 2; g++) {
                uint32_t bf[4][2];
#pragma unroll
                for (int u = 0; u < 4; u++) {
                    uint32_t n = (g * 4 + u) * 8 + (lane & 7);
                    uint32_t c = j * 16 + ((lane >> 3) & 1) * 8;
                    ldsm2(bf[u], kb + n * APB + c * 2);
                }
#pragma unroll
                for (int u = 0; u < 4; u++) mma_f16(s[g * 4 + u], qh[j], bf[u]);
            }
        }
#pragma unroll
        for (int nt = 0; nt < 8; nt++) {
            const int cg = kt * 64 + nt * 8 + qc2;
            if (cg <= r0g)     rs0 += __expf(s[nt][0] * 0.125f);
            if (cg + 1 <= r0g) rs0 += __expf(s[nt][1] * 0.125f);
            if (cg <= r1g)     rs1 += __expf(s[nt][2] * 0.125f);
            if (cg + 1 <= r1g) rs1 += __expf(s[nt][3] * 0.125f);
        }
        __syncthreads();
    }
    rs0 += __shfl_xor_sync(0xFFFFFFFFu, rs0, 1);
    rs0 += __shfl_xor_sync(0xFFFFFFFFu, rs0, 2);
    rs1 += __shfl_xor_sync(0xFFFFFFFFu, rs1, 1);
    rs1 += __shfl_xor_sync(0xFFFFFFFFu, rs1, 2);
    const float ri0 = 1.0f / rs0;
    const float ri1 = 1.0f / rs1;

    // ---------------- pass B: write attn + A@V ----------------
    float o[8][4];
#pragma unroll
    for (int a = 0; a < 8; a++)
#pragma unroll
        for (int c = 0; c < 4; c++) o[a][c] = 0.f;

    // restart pipeline: K+V tile 0
#pragma unroll
    for (int i = 0; i < 2; i++) {
        int idx = tid + i * 256;
        int r = idx >> 3, c = idx & 7;
        uint32_t db = sb + KBASE;
        cpa16(db + r * APB + c * 16, kg + idx * 16);
        cpa16(db + KT_B + r * APB + c * 16, vg + idx * 16);
    }
    CP_COMMIT();

    for (int kt = 0; kt < nkt; kt++) {
        if (kt + 1 < nkt) {
            const uint32_t db = sb + KBASE + ((kt + 1) & 1) * KSTAGE;
            const long long go = (long long)(kt + 1) * 8192;
#pragma unroll
            for (int i = 0; i < 2; i++) {
                int idx = tid + i * 256;
                int r = idx >> 3, c = idx & 7;
                cpa16(db + r * APB + c * 16, kg + go + idx * 16);
                cpa16(db + KT_B + r * APB + c * 16, vg + go + idx * 16);
            }
            CP_COMMIT();
            CP_WAIT(1);
        } else {
            CP_WAIT(0);
        }
        __syncthreads();

        const uint32_t kb = sb + KBASE + (kt & 1) * KSTAGE;
        float s[8][4];
#pragma unroll
        for (int nt = 0; nt < 8; nt++)
#pragma unroll
            for (int c = 0; c < 4; c++) s[nt][c] = 0.f;
#pragma unroll
        for (int j = 0; j < 4; j++) {
#pragma unroll
            for (int g = 0; g < 2; g++) {
                uint32_t bf[4][2];
#pragma unroll
                for (int u = 0; u < 4; u++) {
                    uint32_t n = (g * 4 + u) * 8 + (lane & 7);
                    uint32_t c = j * 16 + ((lane >> 3) & 1) * 8;
                    ldsm2(bf[u], kb + n * APB + c * 2);
                }
#pragma unroll
                for (int u = 0; u < 4; u++) mma_f16(s[g * 4 + u], qh[j], bf[u]);
            }
        }

        // normalized probs -> gmem + fragments for AV
        uint32_t pah[4][4];
#pragma unroll
        for (int nt = 0; nt < 8; nt++) {
            const int cg = kt * 64 + nt * 8 + qc2;
            float e0 = (cg > r0g)     ? 0.f : __expf(s[nt][0] * 0.125f) * ri0;
            float e1 = (cg + 1 > r0g) ? 0.f : __expf(s[nt][1] * 0.125f) * ri0;
            float e2 = (cg > r1g)     ? 0.f : __expf(s[nt][2] * 0.125f) * ri1;
            float e3 = (cg + 1 > r1g) ? 0.f : __expf(s[nt][3] * 0.125f) * ri1;
            *(float2*)&attn_out[(long long)r0g * SS + cg] = make_float2(e0, e1);
            *(float2*)&attn_out[(long long)r1g * SS + cg] = make_float2(e2, e3);
            const int j = nt >> 1, half = (nt & 1) * 2;
            pah[j][half]     = pk(h16(e0), h16(e1));
            pah[j][half + 1] = pk(h16(e2), h16(e3));
        }
        // A@V (single sweep)
#pragma unroll
        for (int j = 0; j < 4; j++) {
#pragma unroll
            for (int g = 0; g < 2; g++) {
                uint32_t vf[4][2];
#pragma unroll
                for (int u = 0; u < 4; u++) {
                    uint32_t key = j * 16 + ((lane >> 3) & 1) * 8 + (lane & 7);
                    ldsm2t(vf[u], kb + KT_B + key * APB + (g * 4 + u) * 16);
                }
#pragma unroll
                for (int u = 0; u < 4; u++) mma_f16(o[g * 4 + u], pah[j], vf[u]);
            }
        }
        __syncthreads();
    }

    // merged-head output single fp16 digit (feeds proj GEMM)
#pragma unroll
    for (int nt2 = 0; nt2 < 8; nt2++) {
        const int col = h * 64 + nt2 * 8 + qc2;
        const long long gr0 = (long long)(b * SS + qbase + wm * 16 + qr);
        *(uint32_t*)&g_ah1[gr0 * DD + col] = pk(h16(o[nt2][0]), h16(o[nt2][1]));
        *(uint32_t*)&g_ah1[(gr0 + 8) * DD + col] = pk(h16(o[nt2][2]), h16(o[nt2][3]));
    }
}

// ====================== launch ==============================================
extern "C" void kernel_launch(void* const* d_in, const int* in_sizes, int n_in,
                              void* d_out, int out_size) {
    const float* x      = (const float*)d_in[0];
    const float* w_attn = (const float*)d_in[1];
    const float* b_attn = (const float*)d_in[2];
    const float* w_proj = (const float*)d_in[3];
    const float* b_proj = (const float*)d_in[4];
    float* out = (float*)d_out;

    __half *x1, *wa, *wp, *ah1;
    cudaGetSymbolAddress((void**)&x1,  g_x1);
    cudaGetSymbolAddress((void**)&wa,  g_wa);
    cudaGetSymbolAddress((void**)&wp,  g_wp);
    cudaGetSymbolAddress((void**)&ah1, g_ah1);

    cudaFuncSetAttribute(gemm_mma<0>, cudaFuncAttributeMaxDynamicSharedMemorySize, GEMM_SMEM);
    cudaFuncSetAttribute(gemm_mma<1>, cudaFuncAttributeMaxDynamicSharedMemorySize, GEMM_SMEM);
    cudaFuncSetAttribute(attn_mma, cudaFuncAttributeMaxDynamicSharedMemorySize, ATTN_SMEM);

    // 0) prepare fp16 operands
    split1<<<(MROWS * DD / 4 + 255) / 256, 256>>>(x, x1, MROWS * DD / 4);
    split_T1<<<dim3(N3 / 32, DD / 32), dim3(32, 8)>>>(w_attn, wa, N3);
    split_T1<<<dim3(DD / 32, DD / 32), dim3(32, 8)>>>(w_proj, wp, DD);

    // 1) QKV projection
    gemm_mma<0><<<dim3(N3 / 128, MROWS / 128), 256, GEMM_SMEM>>>(x1, wa, b_attn, out);

    // 2) attention (incl. upper-triangle fill) -> attn region + ah
    attn_mma<<<dim3(SS / 128, HH, BB), 256, ATTN_SMEM>>>(out);

    // 3) output projection
    gemm_mma<1><<<dim3(DD / 128, MROWS / 128), 256, GEMM_SMEM>>>(ah1, wp, b_proj, out);
}